// round 1
// baseline (speedup 1.0000x reference)
#include <cuda_runtime.h>
#include <cuda_bf16.h>
#include <math.h>

// Problem constants
#define BATCH 2048
#define SEQ   24
#define EMB   256
#define HID   1024
#define VOC   37
#define G4    4096          // 4*HID
#define MROWS (BATCH*SEQ)   // 49152

// ---------------- device scratch (allocation-free rule: __device__ globals) --------
__device__ float g_xg[(size_t)MROWS * G4];   // 805 MB : gate pre-activations (input proj + biases)
__device__ float g_y [(size_t)MROWS * HID];  // 201 MB : layer outputs per timestep
__device__ float g_x [(size_t)MROWS * EMB];  //  48 MB : embedded tokens
__device__ float g_h0a[BATCH * HID];
__device__ float g_h0b[BATCH * HID];
__device__ float g_c0 [BATCH * HID];
__device__ float g_h1a[BATCH * HID];
__device__ float g_h1b[BATCH * HID];
__device__ float g_c1 [BATCH * HID];

__device__ __forceinline__ float sigmoidf_(float x) { return 1.0f / (1.0f + expf(-x)); }

// ---------------- zero-fill ----------------
__global__ void zero_k(float* __restrict__ p, int n) {
    int i = blockIdx.x * 256 + threadIdx.x;
    if (i < n) p[i] = 0.0f;
}

// ---------------- embedding ----------------
__global__ void embed_src_k(const int* __restrict__ src, const float* __restrict__ emb,
                            float* __restrict__ x) {
    int row = blockIdx.x;                      // b*SEQ + s
    int tok = src[row];
    const float4* e = (const float4*)(emb + (size_t)tok * EMB);
    float4* o = (float4*)(x + (size_t)row * EMB);
    o[threadIdx.x] = e[threadIdx.x];           // 64 threads * float4 = 256 floats
}

__global__ void embed_dec_k(const int* __restrict__ tgt, const float* __restrict__ emb,
                            float* __restrict__ x) {
    int row = blockIdx.x;
    int b = row / SEQ, s = row % SEQ;
    int tok = (s == 0) ? 1 : tgt[b * SEQ + s - 1];   // [SOS, tgt[:, :-1]]
    const float4* e = (const float4*)(emb + (size_t)tok * EMB);
    float4* o = (float4*)(x + (size_t)row * EMB);
    o[threadIdx.x] = e[threadIdx.x];
}

// ---------------- input projection GEMM: C[M,4096] = X[M,K] @ W[4096,K]^T + b1 + b2 ----
// BM=128, BN=128, BK=16, 256 threads, 8x8 per thread.
__global__ __launch_bounds__(256) void gemm_bias_k(
    const float* __restrict__ X, const float* __restrict__ W,
    const float* __restrict__ b1, const float* __restrict__ b2,
    float* __restrict__ C, int K)
{
    __shared__ float As[16][132];
    __shared__ float Bs[16][132];
    int tid = threadIdx.x;
    int tx = tid & 15, ty = tid >> 4;
    int m0 = blockIdx.y * 128;
    int n0 = blockIdx.x * 128;

    float acc[8][8];
#pragma unroll
    for (int i = 0; i < 8; i++)
#pragma unroll
        for (int j = 0; j < 8; j++) acc[i][j] = 0.0f;

    for (int k0 = 0; k0 < K; k0 += 16) {
#pragma unroll
        for (int i = 0; i < 2; i++) {
            int l = tid + i * 256;             // 0..511
            int r = l >> 2, c4 = l & 3;
            float4 v = *(const float4*)&X[(size_t)(m0 + r) * K + k0 + c4 * 4];
            As[c4 * 4 + 0][r] = v.x; As[c4 * 4 + 1][r] = v.y;
            As[c4 * 4 + 2][r] = v.z; As[c4 * 4 + 3][r] = v.w;
        }
#pragma unroll
        for (int i = 0; i < 2; i++) {
            int l = tid + i * 256;
            int r = l >> 2, c4 = l & 3;
            float4 v = *(const float4*)&W[(size_t)(n0 + r) * K + k0 + c4 * 4];
            Bs[c4 * 4 + 0][r] = v.x; Bs[c4 * 4 + 1][r] = v.y;
            Bs[c4 * 4 + 2][r] = v.z; Bs[c4 * 4 + 3][r] = v.w;
        }
        __syncthreads();
#pragma unroll
        for (int kk = 0; kk < 16; kk++) {
            float a[8], b[8];
#pragma unroll
            for (int i = 0; i < 8; i++) a[i] = As[kk][ty * 8 + i];
#pragma unroll
            for (int j = 0; j < 8; j++) b[j] = Bs[kk][tx * 8 + j];
#pragma unroll
            for (int i = 0; i < 8; i++)
#pragma unroll
                for (int j = 0; j < 8; j++) acc[i][j] += a[i] * b[j];
        }
        __syncthreads();
    }

#pragma unroll
    for (int i = 0; i < 8; i++) {
        int m = m0 + ty * 8 + i;
#pragma unroll
        for (int j0 = 0; j0 < 8; j0 += 4) {
            int n = n0 + tx * 8 + j0;
            float4 v;
            v.x = acc[i][j0 + 0] + b1[n + 0] + b2[n + 0];
            v.y = acc[i][j0 + 1] + b1[n + 1] + b2[n + 1];
            v.z = acc[i][j0 + 2] + b1[n + 2] + b2[n + 2];
            v.w = acc[i][j0 + 3] + b1[n + 3] + b2[n + 3];
            *(float4*)&C[(size_t)m * G4 + n] = v;
        }
    }
}

// ---------------- fused recurrent step ----------------
// Block computes 128 batch rows x 32 hidden cols x 4 gates (= 128x128 GEMM tile vs W_hh),
// then applies the LSTM cell pointwise in the epilogue.
// Shared B uses interleaved column layout sc = (cc>>1)*8 + gate*2 + (cc&1) so that
// thread tx owns cols {2tx, 2tx+1} for ALL 4 gates -> epilogue is thread-local.
__global__ __launch_bounds__(256) void lstm_step_k(
    const float* __restrict__ h_cur, float* __restrict__ h_nxt,
    float* __restrict__ c_st, const float* __restrict__ Whh,
    const float* __restrict__ xg, float* __restrict__ y, int t)
{
    __shared__ float As[16][132];
    __shared__ float Bs[16][132];
    int tid = threadIdx.x;
    int tx = tid & 15, ty = tid >> 4;
    int m0 = blockIdx.y * 128;     // batch rows
    int n0 = blockIdx.x * 32;      // per-gate hidden col offset

    float acc[8][8];
#pragma unroll
    for (int i = 0; i < 8; i++)
#pragma unroll
        for (int j = 0; j < 8; j++) acc[i][j] = 0.0f;

    for (int k0 = 0; k0 < HID; k0 += 16) {
#pragma unroll
        for (int i = 0; i < 2; i++) {
            int l = tid + i * 256;
            int r = l >> 2, c4 = l & 3;
            float4 v = *(const float4*)&h_cur[(size_t)(m0 + r) * HID + k0 + c4 * 4];
            As[c4 * 4 + 0][r] = v.x; As[c4 * 4 + 1][r] = v.y;
            As[c4 * 4 + 2][r] = v.z; As[c4 * 4 + 3][r] = v.w;
        }
#pragma unroll
        for (int i = 0; i < 2; i++) {
            int l = tid + i * 256;
            int col = l >> 2, c4 = l & 3;      // col 0..127 in W-space
            int gate = col >> 5, cc = col & 31;
            int wrow = gate * HID + n0 + cc;
            float4 v = *(const float4*)&Whh[(size_t)wrow * HID + k0 + c4 * 4];
            int sc = ((cc >> 1) << 3) + (gate << 1) + (cc & 1);
            Bs[c4 * 4 + 0][sc] = v.x; Bs[c4 * 4 + 1][sc] = v.y;
            Bs[c4 * 4 + 2][sc] = v.z; Bs[c4 * 4 + 3][sc] = v.w;
        }
        __syncthreads();
#pragma unroll
        for (int kk = 0; kk < 16; kk++) {
            float a[8], b[8];
#pragma unroll
            for (int i = 0; i < 8; i++) a[i] = As[kk][ty * 8 + i];
#pragma unroll
            for (int j = 0; j < 8; j++) b[j] = Bs[kk][tx * 8 + j];
#pragma unroll
            for (int i = 0; i < 8; i++)
#pragma unroll
                for (int j = 0; j < 8; j++) acc[i][j] += a[i] * b[j];
        }
        __syncthreads();
    }

    // epilogue: acc[i][gate*2+q] is h·Whh^T for column (gate, n0+2tx+q)
#pragma unroll
    for (int i = 0; i < 8; i++) {
        int m = m0 + ty * 8 + i;
        size_t xr = ((size_t)m * SEQ + t) * G4;
#pragma unroll
        for (int q = 0; q < 2; q++) {
            int n = n0 + tx * 2 + q;
            float iv = acc[i][0 + q] + xg[xr + n];
            float fv = acc[i][2 + q] + xg[xr + HID + n];
            float gv = acc[i][4 + q] + xg[xr + 2 * HID + n];
            float ov = acc[i][6 + q] + xg[xr + 3 * HID + n];
            iv = sigmoidf_(iv);
            fv = sigmoidf_(fv);
            gv = tanhf(gv);
            ov = sigmoidf_(ov);
            size_t cidx = (size_t)m * HID + n;
            float cn = fv * c_st[cidx] + iv * gv;
            c_st[cidx] = cn;
            float h = ov * tanhf(cn);
            h_nxt[cidx] = h;
            y[((size_t)m * SEQ + t) * HID + n] = h;
        }
    }
}

// ---------------- final projection: out[M,37] = Y[M,1024] @ fcW[37,1024]^T + fcb ------
__global__ __launch_bounds__(128) void fc_k(
    const float* __restrict__ Y, const float* __restrict__ W,
    const float* __restrict__ bias, float* __restrict__ out)
{
    __shared__ float As[128][33];
    __shared__ float Ws[32][40];
    int tid = threadIdx.x;
    int row0 = blockIdx.x * 128;

    float acc[VOC];
#pragma unroll
    for (int v = 0; v < VOC; v++) acc[v] = 0.0f;

    for (int k0 = 0; k0 < HID; k0 += 32) {
        // load 128 rows x 32 cols of Y, coalesced via float4
#pragma unroll
        for (int i = 0; i < 8; i++) {
            int f = i * 128 + tid;             // 0..1023 float4 slots
            int r = f >> 3, k4 = f & 7;
            float4 v = *(const float4*)&Y[(size_t)(row0 + r) * HID + k0 + k4 * 4];
            As[r][k4 * 4 + 0] = v.x; As[r][k4 * 4 + 1] = v.y;
            As[r][k4 * 4 + 2] = v.z; As[r][k4 * 4 + 3] = v.w;
        }
        // load 37 x 32 of W
        for (int l = tid; l < VOC * 32; l += 128) {
            int v = l >> 5, kk = l & 31;
            Ws[kk][v] = W[(size_t)v * HID + k0 + kk];
        }
        __syncthreads();
#pragma unroll
        for (int kk = 0; kk < 32; kk++) {
            float a = As[tid][kk];
#pragma unroll
            for (int v = 0; v < VOC; v++) acc[v] += a * Ws[kk][v];
        }
        __syncthreads();
    }

    int row = row0 + tid;
#pragma unroll
    for (int v = 0; v < VOC; v++)
        out[(size_t)row * VOC + v] = acc[v] + bias[v];
}

// ---------------- driver ----------------
extern "C" void kernel_launch(void* const* d_in, const int* in_sizes, int n_in,
                              void* d_out, int out_size)
{
    const int*   src    = (const int*)  d_in[0];
    const int*   tgt    = (const int*)  d_in[1];
    const float* emb    = (const float*)d_in[2];
    const float* eW_ih0 = (const float*)d_in[3];
    const float* eW_hh0 = (const float*)d_in[4];
    const float* eb_ih0 = (const float*)d_in[5];
    const float* eb_hh0 = (const float*)d_in[6];
    const float* eW_ih1 = (const float*)d_in[7];
    const float* eW_hh1 = (const float*)d_in[8];
    const float* eb_ih1 = (const float*)d_in[9];
    const float* eb_hh1 = (const float*)d_in[10];
    const float* dW_ih0 = (const float*)d_in[11];
    const float* dW_hh0 = (const float*)d_in[12];
    const float* db_ih0 = (const float*)d_in[13];
    const float* db_hh0 = (const float*)d_in[14];
    const float* dW_ih1 = (const float*)d_in[15];
    const float* dW_hh1 = (const float*)d_in[16];
    const float* db_ih1 = (const float*)d_in[17];
    const float* db_hh1 = (const float*)d_in[18];
    const float* fcW    = (const float*)d_in[19];
    const float* fcb    = (const float*)d_in[20];
    float* out = (float*)d_out;

    float *xg, *y, *x, *h0a, *h0b, *c0, *h1a, *h1b, *c1;
    cudaGetSymbolAddress((void**)&xg,  g_xg);
    cudaGetSymbolAddress((void**)&y,   g_y);
    cudaGetSymbolAddress((void**)&x,   g_x);
    cudaGetSymbolAddress((void**)&h0a, g_h0a);
    cudaGetSymbolAddress((void**)&h0b, g_h0b);
    cudaGetSymbolAddress((void**)&c0,  g_c0);
    cudaGetSymbolAddress((void**)&h1a, g_h1a);
    cudaGetSymbolAddress((void**)&h1b, g_h1b);
    cudaGetSymbolAddress((void**)&c1,  g_c1);

    const int NSTATE = BATCH * HID;
    int zb = (NSTATE + 255) / 256;
    zero_k<<<zb, 256>>>(h0a, NSTATE);
    zero_k<<<zb, 256>>>(c0,  NSTATE);
    zero_k<<<zb, 256>>>(h1a, NSTATE);
    zero_k<<<zb, 256>>>(c1,  NSTATE);

    dim3 ggrid(G4 / 128, MROWS / 128);     // (32, 384)
    dim3 sgrid(HID / 32, BATCH / 128);     // (32, 16)

    float *hc0 = h0a, *hn0 = h0b;
    float *hc1 = h1a, *hn1 = h1b;

    // ---- encoder layer 0 ----
    embed_src_k<<<MROWS, 64>>>(src, emb, x);
    gemm_bias_k<<<ggrid, 256>>>(x, eW_ih0, eb_ih0, eb_hh0, xg, EMB);
    for (int t = 0; t < SEQ; t++) {
        lstm_step_k<<<sgrid, 256>>>(hc0, hn0, c0, eW_hh0, xg, y, t);
        float* tmp = hc0; hc0 = hn0; hn0 = tmp;
    }
    // ---- encoder layer 1 ----
    gemm_bias_k<<<ggrid, 256>>>(y, eW_ih1, eb_ih1, eb_hh1, xg, HID);
    for (int t = 0; t < SEQ; t++) {
        lstm_step_k<<<sgrid, 256>>>(hc1, hn1, c1, eW_hh1, xg, y, t);
        float* tmp = hc1; hc1 = hn1; hn1 = tmp;
    }
    // ---- decoder layer 0 (states carry over from encoder) ----
    embed_dec_k<<<MROWS, 64>>>(tgt, emb, x);
    gemm_bias_k<<<ggrid, 256>>>(x, dW_ih0, db_ih0, db_hh0, xg, EMB);
    for (int t = 0; t < SEQ; t++) {
        lstm_step_k<<<sgrid, 256>>>(hc0, hn0, c0, dW_hh0, xg, y, t);
        float* tmp = hc0; hc0 = hn0; hn0 = tmp;
    }
    // ---- decoder layer 1 ----
    gemm_bias_k<<<ggrid, 256>>>(y, dW_ih1, db_ih1, db_hh1, xg, HID);
    for (int t = 0; t < SEQ; t++) {
        lstm_step_k<<<sgrid, 256>>>(hc1, hn1, c1, dW_hh1, xg, y, t);
        float* tmp = hc1; hc1 = hn1; hn1 = tmp;
    }
    // ---- output projection ----
    fc_k<<<MROWS / 128, 128>>>(y, fcW, fcb, out);
}

// round 2
// speedup vs baseline: 1.3167x; 1.3167x over previous
#include <cuda_runtime.h>
#include <cuda_bf16.h>
#include <mma.h>
#include <math.h>

using namespace nvcuda;

// Problem constants
#define BATCH 2048
#define SEQ   24
#define EMB   256
#define HID   1024
#define VOC   37
#define G4    4096
#define MROWS (BATCH*SEQ)   // 49152

#define LDA 40    // shared stage leading dim (bf16 elems): 80B, multiple of 16B
#define LDC 132   // shared epilogue C leading dim (floats): 528B, multiple of 16B
#define SMEM_BYTES (128*LDC*4)   // 67584: epilogue dominates (stage needs 4*128*40*2=40960)

// ---------------- device scratch ----------------
__device__ float g_xg[(size_t)MROWS * G4];            // 805 MB gate preactivations
__device__ float g_y [(size_t)MROWS * HID];           // 201 MB fp32 outputs (for FC)
__device__ __nv_bfloat16 g_yhi[(size_t)MROWS * HID];  // 100 MB
__device__ __nv_bfloat16 g_ylo[(size_t)MROWS * HID];
__device__ __nv_bfloat16 g_xhi[(size_t)MROWS * EMB];  // 25 MB
__device__ __nv_bfloat16 g_xlo[(size_t)MROWS * EMB];
__device__ __nv_bfloat16 g_whi[(size_t)8 * G4 * HID]; // 67 MB weight pool hi
__device__ __nv_bfloat16 g_wlo[(size_t)8 * G4 * HID]; // 67 MB weight pool lo
// LSTM states (hi/lo bf16 h, double buffered; fp32 c)
__device__ __nv_bfloat16 g_h0hi_a[BATCH*HID], g_h0lo_a[BATCH*HID];
__device__ __nv_bfloat16 g_h0hi_b[BATCH*HID], g_h0lo_b[BATCH*HID];
__device__ __nv_bfloat16 g_h1hi_a[BATCH*HID], g_h1lo_a[BATCH*HID];
__device__ __nv_bfloat16 g_h1hi_b[BATCH*HID], g_h1lo_b[BATCH*HID];
__device__ float g_c0[BATCH*HID], g_c1[BATCH*HID];

// ---------------- helpers ----------------
__device__ __forceinline__ float sig_(float x)  { return 1.0f / (1.0f + __expf(-x)); }
__device__ __forceinline__ float tanh_(float x) { float t = __expf(2.0f * x); return 1.0f - 2.0f / (t + 1.0f); }

__device__ __forceinline__ void split2(float v, __nv_bfloat16& hi, __nv_bfloat16& lo) {
    hi = __float2bfloat16(v);
    lo = __float2bfloat16(v - __bfloat162float(hi));
}

// ---------------- small kernels ----------------
__global__ void zero_u4(uint4* __restrict__ p, int n) {
    int i = blockIdx.x * 256 + threadIdx.x;
    if (i < n) p[i] = make_uint4(0, 0, 0, 0);
}

__global__ void conv_k(const float* __restrict__ s, __nv_bfloat16* __restrict__ hi,
                       __nv_bfloat16* __restrict__ lo, int n) {
    int i = (blockIdx.x * 256 + threadIdx.x) * 4;
    if (i < n) {
        float4 v = *(const float4*)(s + i);
        __nv_bfloat16 h0, l0, h1, l1, h2, l2, h3, l3;
        split2(v.x, h0, l0); split2(v.y, h1, l1);
        split2(v.z, h2, l2); split2(v.w, h3, l3);
        __nv_bfloat162* ph = (__nv_bfloat162*)(hi + i);
        __nv_bfloat162* pl = (__nv_bfloat162*)(lo + i);
        ph[0] = __nv_bfloat162{h0, h1}; ph[1] = __nv_bfloat162{h2, h3};
        pl[0] = __nv_bfloat162{l0, l1}; pl[1] = __nv_bfloat162{l2, l3};
    }
}

__global__ void embed_src_k(const int* __restrict__ src, const float* __restrict__ emb,
                            __nv_bfloat16* __restrict__ xhi, __nv_bfloat16* __restrict__ xlo) {
    int row = blockIdx.x;
    int tok = src[row];
    float4 v = ((const float4*)(emb + (size_t)tok * EMB))[threadIdx.x];
    int i = row * EMB + threadIdx.x * 4;
    __nv_bfloat16 h0, l0, h1, l1, h2, l2, h3, l3;
    split2(v.x, h0, l0); split2(v.y, h1, l1); split2(v.z, h2, l2); split2(v.w, h3, l3);
    __nv_bfloat162* ph = (__nv_bfloat162*)(xhi + i);
    __nv_bfloat162* pl = (__nv_bfloat162*)(xlo + i);
    ph[0] = __nv_bfloat162{h0, h1}; ph[1] = __nv_bfloat162{h2, h3};
    pl[0] = __nv_bfloat162{l0, l1}; pl[1] = __nv_bfloat162{l2, l3};
}

__global__ void embed_dec_k(const int* __restrict__ tgt, const float* __restrict__ emb,
                            __nv_bfloat16* __restrict__ xhi, __nv_bfloat16* __restrict__ xlo) {
    int row = blockIdx.x;
    int b = row / SEQ, s = row % SEQ;
    int tok = (s == 0) ? 1 : tgt[b * SEQ + s - 1];
    float4 v = ((const float4*)(emb + (size_t)tok * EMB))[threadIdx.x];
    int i = row * EMB + threadIdx.x * 4;
    __nv_bfloat16 h0, l0, h1, l1, h2, l2, h3, l3;
    split2(v.x, h0, l0); split2(v.y, h1, l1); split2(v.z, h2, l2); split2(v.w, h3, l3);
    __nv_bfloat162* ph = (__nv_bfloat162*)(xhi + i);
    __nv_bfloat162* pl = (__nv_bfloat162*)(xlo + i);
    ph[0] = __nv_bfloat162{h0, h1}; ph[1] = __nv_bfloat162{h2, h3};
    pl[0] = __nv_bfloat162{l0, l1}; pl[1] = __nv_bfloat162{l2, l3};
}

// ---------------- split-bf16 tensor-core GEMM core ----------------
// Computes a 128x128 tile of X[M,K] @ W[.,K]^T in fp32 via 3-pass hi/lo bf16 WMMA,
// leaving the result staged in shared memory (sC, ld=LDC).
// STEP=1: tile col c maps to W row gate*HID + n0 + cc with 16-wide gate-chunk
//         interleave: gate=(c>>4)&3, cc=(c&15)|(((c>>6)&1)<<4).
// STEP=0: tile col c maps to W row n0 + c.
template<int STEP>
__device__ __forceinline__ void gemm_core(
    const __nv_bfloat16* __restrict__ Xhi, const __nv_bfloat16* __restrict__ Xlo,
    const __nv_bfloat16* __restrict__ Whi, const __nv_bfloat16* __restrict__ Wlo,
    int K, int m0, int n0, char* smem)
{
    __nv_bfloat16* sAhi = (__nv_bfloat16*)smem;
    __nv_bfloat16* sAlo = sAhi + 128 * LDA;
    __nv_bfloat16* sBhi = sAlo + 128 * LDA;
    __nv_bfloat16* sBlo = sBhi + 128 * LDA;
    float* sC = (float*)smem;

    int tid = threadIdx.x;
    int wid = tid >> 5;
    int wm = (wid >> 1) * 32;
    int wn = (wid & 1) * 64;

    wmma::fragment<wmma::accumulator, 16, 16, 16, float> acc[2][4];
#pragma unroll
    for (int i = 0; i < 2; i++)
#pragma unroll
        for (int j = 0; j < 4; j++) wmma::fill_fragment(acc[i][j], 0.0f);

    for (int k0 = 0; k0 < K; k0 += 32) {
#pragma unroll
        for (int i = 0; i < 4; i++) {
            int idx = tid + i * 256;   // 1024 uint2 slots = 128 rows x 8 quads
            int r = idx >> 3, q = idx & 7;
            *(uint2*)&sAhi[r * LDA + q * 4] = *(const uint2*)(Xhi + (size_t)(m0 + r) * K + k0 + q * 4);
            *(uint2*)&sAlo[r * LDA + q * 4] = *(const uint2*)(Xlo + (size_t)(m0 + r) * K + k0 + q * 4);
            int c = r;
            int wrow;
            if (STEP) {
                int gate = (c >> 4) & 3;
                int cc = (c & 15) | (((c >> 6) & 1) << 4);
                wrow = gate * HID + n0 + cc;
            } else {
                wrow = n0 + c;
            }
            *(uint2*)&sBhi[c * LDA + q * 4] = *(const uint2*)(Whi + (size_t)wrow * K + k0 + q * 4);
            *(uint2*)&sBlo[c * LDA + q * 4] = *(const uint2*)(Wlo + (size_t)wrow * K + k0 + q * 4);
        }
        __syncthreads();
#pragma unroll
        for (int kk = 0; kk < 32; kk += 16) {
            wmma::fragment<wmma::matrix_a, 16, 16, 16, __nv_bfloat16, wmma::row_major> ah[2], al[2];
            wmma::fragment<wmma::matrix_b, 16, 16, 16, __nv_bfloat16, wmma::col_major> bh[4], bl[4];
#pragma unroll
            for (int i = 0; i < 2; i++) {
                wmma::load_matrix_sync(ah[i], sAhi + (wm + 16 * i) * LDA + kk, LDA);
                wmma::load_matrix_sync(al[i], sAlo + (wm + 16 * i) * LDA + kk, LDA);
            }
#pragma unroll
            for (int j = 0; j < 4; j++) {
                wmma::load_matrix_sync(bh[j], sBhi + (wn + 16 * j) * LDA + kk, LDA);
                wmma::load_matrix_sync(bl[j], sBlo + (wn + 16 * j) * LDA + kk, LDA);
            }
#pragma unroll
            for (int i = 0; i < 2; i++)
#pragma unroll
                for (int j = 0; j < 4; j++) {
                    wmma::mma_sync(acc[i][j], ah[i], bh[j], acc[i][j]);
                    wmma::mma_sync(acc[i][j], ah[i], bl[j], acc[i][j]);
                    wmma::mma_sync(acc[i][j], al[i], bh[j], acc[i][j]);
                }
        }
        __syncthreads();
    }
#pragma unroll
    for (int i = 0; i < 2; i++)
#pragma unroll
        for (int j = 0; j < 4; j++)
            wmma::store_matrix_sync(sC + (wm + 16 * i) * LDC + wn + 16 * j, acc[i][j],
                                    LDC, wmma::mem_row_major);
    __syncthreads();
}

// ---------------- input projection: xg = X @ W^T + b_ih + b_hh ----------------
__global__ __launch_bounds__(256) void gemm_in_k(
    const __nv_bfloat16* __restrict__ Xhi, const __nv_bfloat16* __restrict__ Xlo,
    const __nv_bfloat16* __restrict__ Whi, const __nv_bfloat16* __restrict__ Wlo,
    const float* __restrict__ b1, const float* __restrict__ b2,
    float* __restrict__ C, int K)
{
    extern __shared__ char smem[];
    int m0 = blockIdx.y * 128, n0 = blockIdx.x * 128;
    gemm_core<0>(Xhi, Xlo, Whi, Wlo, K, m0, n0, smem);

    float* sC = (float*)smem;
    int tid = threadIdx.x;
#pragma unroll
    for (int i = 0; i < 16; i++) {
        int idx = tid + i * 256;       // 4096 float4 = 128x128 floats
        int r = idx >> 5, q = idx & 31;
        int n = n0 + q * 4;
        float4 v = *(float4*)&sC[r * LDC + q * 4];
        v.x += b1[n + 0] + b2[n + 0];
        v.y += b1[n + 1] + b2[n + 1];
        v.z += b1[n + 2] + b2[n + 2];
        v.w += b1[n + 3] + b2[n + 3];
        *(float4*)&C[(size_t)(m0 + r) * G4 + n] = v;
    }
}

// ---------------- fused LSTM recurrent step (tensor core) ----------------
__global__ __launch_bounds__(256) void lstm_step_tc(
    const __nv_bfloat16* __restrict__ hhi_c, const __nv_bfloat16* __restrict__ hlo_c,
    __nv_bfloat16* __restrict__ hhi_n, __nv_bfloat16* __restrict__ hlo_n,
    float* __restrict__ c_st,
    const __nv_bfloat16* __restrict__ Whi, const __nv_bfloat16* __restrict__ Wlo,
    const float* __restrict__ xg, float* __restrict__ y,
    __nv_bfloat16* __restrict__ yhi, __nv_bfloat16* __restrict__ ylo, int t)
{
    extern __shared__ char smem[];
    int m0 = blockIdx.y * 128, n0 = blockIdx.x * 32;
    gemm_core<1>(hhi_c, hlo_c, Whi, Wlo, HID, m0, n0, smem);

    float* sC = (float*)smem;
    int tid = threadIdx.x;
#pragma unroll
    for (int i = 0; i < 16; i++) {
        int idx = tid + i * 256;       // 4096 cells = 128 m x 32 cc
        int m = idx >> 5, cc = idx & 31;
        int cl = (cc & 15) + ((cc >> 4) << 6);
        float di = sC[m * LDC + cl];
        float df = sC[m * LDC + cl + 16];
        float dg = sC[m * LDC + cl + 32];
        float dv = sC[m * LDC + cl + 48];
        int gm = m0 + m;
        int n = n0 + cc;
        size_t xr = ((size_t)gm * SEQ + t) * G4 + n;
        float iv = sig_ (di + xg[xr]);
        float fv = sig_ (df + xg[xr + HID]);
        float gv = tanh_(dg + xg[xr + 2 * HID]);
        float ov = sig_ (dv + xg[xr + 3 * HID]);
        size_t ci = (size_t)gm * HID + n;
        float cn = fv * c_st[ci] + iv * gv;
        c_st[ci] = cn;
        float h = ov * tanh_(cn);
        size_t yi = ((size_t)gm * SEQ + t) * HID + n;
        y[yi] = h;
        __nv_bfloat16 hh, hl;
        split2(h, hh, hl);
        hhi_n[ci] = hh; hlo_n[ci] = hl;
        yhi[yi] = hh;   ylo[yi] = hl;
    }
}

// ---------------- final projection: out[M,37] = Y @ fcW^T + fcb ----------------
__global__ __launch_bounds__(128) void fc_k(
    const float* __restrict__ Y, const float* __restrict__ W,
    const float* __restrict__ bias, float* __restrict__ out)
{
    __shared__ float As[128][33];
    __shared__ float Ws[32][40];
    int tid = threadIdx.x;
    int row0 = blockIdx.x * 128;

    float acc[VOC];
#pragma unroll
    for (int v = 0; v < VOC; v++) acc[v] = 0.0f;

    for (int k0 = 0; k0 < HID; k0 += 32) {
#pragma unroll
        for (int i = 0; i < 8; i++) {
            int f = i * 128 + tid;
            int r = f >> 3, k4 = f & 7;
            float4 v = *(const float4*)&Y[(size_t)(row0 + r) * HID + k0 + k4 * 4];
            As[r][k4 * 4 + 0] = v.x; As[r][k4 * 4 + 1] = v.y;
            As[r][k4 * 4 + 2] = v.z; As[r][k4 * 4 + 3] = v.w;
        }
        for (int l = tid; l < VOC * 32; l += 128) {
            int v = l >> 5, kk = l & 31;
            Ws[kk][v] = W[(size_t)v * HID + k0 + kk];
        }
        __syncthreads();
#pragma unroll
        for (int kk = 0; kk < 32; kk++) {
            float a = As[tid][kk];
#pragma unroll
            for (int v = 0; v < VOC; v++) acc[v] += a * Ws[kk][v];
        }
        __syncthreads();
    }
    int row = row0 + tid;
#pragma unroll
    for (int v = 0; v < VOC; v++)
        out[(size_t)row * VOC + v] = acc[v] + bias[v];
}

// ---------------- driver ----------------
extern "C" void kernel_launch(void* const* d_in, const int* in_sizes, int n_in,
                              void* d_out, int out_size)
{
    const int*   src    = (const int*)  d_in[0];
    const int*   tgt    = (const int*)  d_in[1];
    const float* emb    = (const float*)d_in[2];
    const float* eW_ih0 = (const float*)d_in[3];
    const float* eW_hh0 = (const float*)d_in[4];
    const float* eb_ih0 = (const float*)d_in[5];
    const float* eb_hh0 = (const float*)d_in[6];
    const float* eW_ih1 = (const float*)d_in[7];
    const float* eW_hh1 = (const float*)d_in[8];
    const float* eb_ih1 = (const float*)d_in[9];
    const float* eb_hh1 = (const float*)d_in[10];
    const float* dW_ih0 = (const float*)d_in[11];
    const float* dW_hh0 = (const float*)d_in[12];
    const float* db_ih0 = (const float*)d_in[13];
    const float* db_hh0 = (const float*)d_in[14];
    const float* dW_ih1 = (const float*)d_in[15];
    const float* dW_hh1 = (const float*)d_in[16];
    const float* db_ih1 = (const float*)d_in[17];
    const float* db_hh1 = (const float*)d_in[18];
    const float* fcW    = (const float*)d_in[19];
    const float* fcb    = (const float*)d_in[20];
    float* out = (float*)d_out;

    static_assert(SMEM_BYTES >= 4 * 128 * LDA * 2, "stage fits in epilogue smem");
    cudaFuncSetAttribute(gemm_in_k,    cudaFuncAttributeMaxDynamicSharedMemorySize, SMEM_BYTES);
    cudaFuncSetAttribute(lstm_step_tc, cudaFuncAttributeMaxDynamicSharedMemorySize, SMEM_BYTES);

    float *xg, *y, *c0, *c1;
    __nv_bfloat16 *yhi, *ylo, *xhi, *xlo, *whi, *wlo;
    __nv_bfloat16 *h0hi_a, *h0lo_a, *h0hi_b, *h0lo_b, *h1hi_a, *h1lo_a, *h1hi_b, *h1lo_b;
    cudaGetSymbolAddress((void**)&xg,  g_xg);
    cudaGetSymbolAddress((void**)&y,   g_y);
    cudaGetSymbolAddress((void**)&yhi, g_yhi);
    cudaGetSymbolAddress((void**)&ylo, g_ylo);
    cudaGetSymbolAddress((void**)&xhi, g_xhi);
    cudaGetSymbolAddress((void**)&xlo, g_xlo);
    cudaGetSymbolAddress((void**)&whi, g_whi);
    cudaGetSymbolAddress((void**)&wlo, g_wlo);
    cudaGetSymbolAddress((void**)&h0hi_a, g_h0hi_a);
    cudaGetSymbolAddress((void**)&h0lo_a, g_h0lo_a);
    cudaGetSymbolAddress((void**)&h0hi_b, g_h0hi_b);
    cudaGetSymbolAddress((void**)&h0lo_b, g_h0lo_b);
    cudaGetSymbolAddress((void**)&h1hi_a, g_h1hi_a);
    cudaGetSymbolAddress((void**)&h1lo_a, g_h1lo_a);
    cudaGetSymbolAddress((void**)&h1hi_b, g_h1hi_b);
    cudaGetSymbolAddress((void**)&h1lo_b, g_h1lo_b);
    cudaGetSymbolAddress((void**)&c0, g_c0);
    cudaGetSymbolAddress((void**)&c1, g_c1);

    const size_t WSLOT = (size_t)G4 * HID;   // weight pool slot stride (elements)

    // ---- weight + embedding conversion to split bf16 ----
    {
        int n1 = G4 * EMB, n2 = G4 * HID;
        int b1 = n1 / 1024, b2 = n2 / 1024;
        conv_k<<<b1, 256>>>(eW_ih0, whi + 0 * WSLOT, wlo + 0 * WSLOT, n1);
        conv_k<<<b2, 256>>>(eW_hh0, whi + 1 * WSLOT, wlo + 1 * WSLOT, n2);
        conv_k<<<b2, 256>>>(eW_ih1, whi + 2 * WSLOT, wlo + 2 * WSLOT, n2);
        conv_k<<<b2, 256>>>(eW_hh1, whi + 3 * WSLOT, wlo + 3 * WSLOT, n2);
        conv_k<<<b1, 256>>>(dW_ih0, whi + 4 * WSLOT, wlo + 4 * WSLOT, n1);
        conv_k<<<b2, 256>>>(dW_hh0, whi + 5 * WSLOT, wlo + 5 * WSLOT, n2);
        conv_k<<<b2, 256>>>(dW_ih1, whi + 6 * WSLOT, wlo + 6 * WSLOT, n2);
        conv_k<<<b2, 256>>>(dW_hh1, whi + 7 * WSLOT, wlo + 7 * WSLOT, n2);
    }

    // ---- zero initial states ----
    {
        int nb = BATCH * HID * 2 / 16;   // bf16 arrays in uint4 units
        int nf = BATCH * HID * 4 / 16;   // fp32 arrays in uint4 units
        zero_u4<<<(nb + 255) / 256, 256>>>((uint4*)h0hi_a, nb);
        zero_u4<<<(nb + 255) / 256, 256>>>((uint4*)h0lo_a, nb);
        zero_u4<<<(nb + 255) / 256, 256>>>((uint4*)h1hi_a, nb);
        zero_u4<<<(nb + 255) / 256, 256>>>((uint4*)h1lo_a, nb);
        zero_u4<<<(nf + 255) / 256, 256>>>((uint4*)c0, nf);
        zero_u4<<<(nf + 255) / 256, 256>>>((uint4*)c1, nf);
    }

    dim3 ggrid(G4 / 128, MROWS / 128);   // (32, 384)
    dim3 sgrid(HID / 32, BATCH / 128);   // (32, 16)

    __nv_bfloat16 *hc0h = h0hi_a, *hc0l = h0lo_a, *hn0h = h0hi_b, *hn0l = h0lo_b;
    __nv_bfloat16 *hc1h = h1hi_a, *hc1l = h1lo_a, *hn1h = h1hi_b, *hn1l = h1lo_b;

    // ---- encoder layer 0 ----
    embed_src_k<<<MROWS, 64>>>(src, emb, xhi, xlo);
    gemm_in_k<<<ggrid, 256, SMEM_BYTES>>>(xhi, xlo, whi + 0 * WSLOT, wlo + 0 * WSLOT,
                                          eb_ih0, eb_hh0, xg, EMB);
    for (int t = 0; t < SEQ; t++) {
        lstm_step_tc<<<sgrid, 256, SMEM_BYTES>>>(hc0h, hc0l, hn0h, hn0l, c0,
                                                 whi + 1 * WSLOT, wlo + 1 * WSLOT,
                                                 xg, y, yhi, ylo, t);
        __nv_bfloat16* t1 = hc0h; hc0h = hn0h; hn0h = t1;
        __nv_bfloat16* t2 = hc0l; hc0l = hn0l; hn0l = t2;
    }
    // ---- encoder layer 1 ----
    gemm_in_k<<<ggrid, 256, SMEM_BYTES>>>(yhi, ylo, whi + 2 * WSLOT, wlo + 2 * WSLOT,
                                          eb_ih1, eb_hh1, xg, HID);
    for (int t = 0; t < SEQ; t++) {
        lstm_step_tc<<<sgrid, 256, SMEM_BYTES>>>(hc1h, hc1l, hn1h, hn1l, c1,
                                                 whi + 3 * WSLOT, wlo + 3 * WSLOT,
                                                 xg, y, yhi, ylo, t);
        __nv_bfloat16* t1 = hc1h; hc1h = hn1h; hn1h = t1;
        __nv_bfloat16* t2 = hc1l; hc1l = hn1l; hn1l = t2;
    }
    // ---- decoder layer 0 (states carry over) ----
    embed_dec_k<<<MROWS, 64>>>(tgt, emb, xhi, xlo);
    gemm_in_k<<<ggrid, 256, SMEM_BYTES>>>(xhi, xlo, whi + 4 * WSLOT, wlo + 4 * WSLOT,
                                          db_ih0, db_hh0, xg, EMB);
    for (int t = 0; t < SEQ; t++) {
        lstm_step_tc<<<sgrid, 256, SMEM_BYTES>>>(hc0h, hc0l, hn0h, hn0l, c0,
                                                 whi + 5 * WSLOT, wlo + 5 * WSLOT,
                                                 xg, y, yhi, ylo, t);
        __nv_bfloat16* t1 = hc0h; hc0h = hn0h; hn0h = t1;
        __nv_bfloat16* t2 = hc0l; hc0l = hn0l; hn0l = t2;
    }
    // ---- decoder layer 1 ----
    gemm_in_k<<<ggrid, 256, SMEM_BYTES>>>(yhi, ylo, whi + 6 * WSLOT, wlo + 6 * WSLOT,
                                          db_ih1, db_hh1, xg, HID);
    for (int t = 0; t < SEQ; t++) {
        lstm_step_tc<<<sgrid, 256, SMEM_BYTES>>>(hc1h, hc1l, hn1h, hn1l, c1,
                                                 whi + 7 * WSLOT, wlo + 7 * WSLOT,
                                                 xg, y, yhi, ylo, t);
        __nv_bfloat16* t1 = hc1h; hc1h = hn1h; hn1h = t1;
        __nv_bfloat16* t2 = hc1l; hc1l = hn1l; hn1l = t2;
    }
    // ---- output projection ----
    fc_k<<<MROWS / 128, 128>>>(y, fcW, fcb, out);
}

// round 5
// speedup vs baseline: 2.0014x; 1.5200x over previous
#include <cuda_runtime.h>
#include <cuda_bf16.h>
#include <mma.h>
#include <cstdint>
#include <math.h>

using namespace nvcuda;

// Problem constants
#define BATCH 2048
#define SEQ   24
#define EMB   256
#define HID   1024
#define VOC   37
#define G4    4096
#define MROWS (BATCH*SEQ)   // 49152

#define LDA 40              // stage leading dim (bf16): 80B rows, conflict-free LDSM
#define LDC 132             // epilogue C leading dim (floats)
#define ARRB (128*LDA*2)    // 10240 bytes per matrix per stage
#define STG  (4*ARRB)       // 40960 bytes per stage (Ahi,Alo,Bhi,Blo)
#define SMEM_ALLOC (2*STG)  // 81920 (epilogue sC needs 67584, reuses this)

// ---------------- device scratch ----------------
__device__ float g_xg[(size_t)MROWS * G4];            // gate preactivations (layer-1 passes only)
__device__ float g_y [(size_t)MROWS * HID];           // fp32 outputs (final FC input)
__device__ __nv_bfloat16 g_yhi[(size_t)MROWS * HID];
__device__ __nv_bfloat16 g_ylo[(size_t)MROWS * HID];
__device__ __nv_bfloat16 g_whi[(size_t)6 * G4 * HID]; // 6 weight slots (hh0e,ih1e,hh1e,hh0d,ih1d,hh1d)
__device__ __nv_bfloat16 g_wlo[(size_t)6 * G4 * HID];
__device__ float g_tabE[VOC * G4];                    // layer-0 gate tables (exact fp32)
__device__ float g_tabD[VOC * G4];
__device__ int   g_dtok[MROWS];                       // decoder input tokens
__device__ __nv_bfloat16 g_h0hi_a[BATCH*HID], g_h0lo_a[BATCH*HID];
__device__ __nv_bfloat16 g_h0hi_b[BATCH*HID], g_h0lo_b[BATCH*HID];
__device__ __nv_bfloat16 g_h1hi_a[BATCH*HID], g_h1lo_a[BATCH*HID];
__device__ __nv_bfloat16 g_h1hi_b[BATCH*HID], g_h1lo_b[BATCH*HID];
__device__ float g_c0[BATCH*HID], g_c1[BATCH*HID];

// ---------------- helpers ----------------
__device__ __forceinline__ float sig_(float x)  { return 1.0f / (1.0f + __expf(-x)); }
__device__ __forceinline__ float tanh_(float x) { float t = __expf(2.0f * x); return 1.0f - 2.0f / (t + 1.0f); }

__device__ __forceinline__ void split2(float v, __nv_bfloat16& hi, __nv_bfloat16& lo) {
    hi = __float2bfloat16(v);
    lo = __float2bfloat16(v - __bfloat162float(hi));
}

__device__ __forceinline__ uint32_t smem_u32(const void* p) {
    uint32_t a;
    asm("{ .reg .u64 t; cvta.to.shared.u64 t, %1; cvt.u32.u64 %0, t; }" : "=r"(a) : "l"(p));
    return a;
}

__device__ __forceinline__ void cpa16(uint32_t dst, const void* src) {
    asm volatile("cp.async.cg.shared.global [%0], [%1], 16;" :: "r"(dst), "l"(src) : "memory");
}

// ---------------- stage loader (cp.async) ----------------
// STEP=1 (lstm): B tile row r -> W row gate*HID + n0 + cc, gate=(r>>4)&3, cc=(r&15)|(((r>>6)&1)<<4)
// STEP=0 (proj): B tile row r -> W row n0 + r
template<int STEP>
__device__ __forceinline__ void stage_load(
    const __nv_bfloat16* __restrict__ Xhi, const __nv_bfloat16* __restrict__ Xlo,
    const __nv_bfloat16* __restrict__ Whi, const __nv_bfloat16* __restrict__ Wlo,
    int K, int m0, int n0, int k0, uint32_t sbase)
{
    int tid = threadIdx.x;
#pragma unroll
    for (int i = 0; i < 8; i++) {
        int idx = tid + (i << 8);     // 0..2047
        int arr = idx >> 9;           // 0 Ahi, 1 Alo, 2 Bhi, 3 Blo
        int r   = (idx >> 2) & 127;
        int c   = idx & 3;            // 16B chunk within 64B row
        const __nv_bfloat16* src;
        if (arr == 0)      src = Xhi + (size_t)(m0 + r) * K + k0 + (c << 3);
        else if (arr == 1) src = Xlo + (size_t)(m0 + r) * K + k0 + (c << 3);
        else {
            int wrow;
            if (STEP) { int g = (r >> 4) & 3; int cc = (r & 15) | (((r >> 6) & 1) << 4); wrow = g * HID + n0 + cc; }
            else      { wrow = n0 + r; }
            src = (arr == 3 ? Wlo : Whi) + (size_t)wrow * K + k0 + (c << 3);
        }
        uint32_t dst = sbase + arr * ARRB + r * (LDA * 2) + (c << 4);
        cpa16(dst, src);
    }
    asm volatile("cp.async.commit_group;" ::: "memory");
}

// ---------------- split-bf16 GEMM core (double-buffered) ----------------
// 128x128 tile of X[M,K] @ W[.,K]^T, fp32 result staged into sC (reuses smem).
template<int STEP>
__device__ __forceinline__ void gemm_core(
    const __nv_bfloat16* __restrict__ Xhi, const __nv_bfloat16* __restrict__ Xlo,
    const __nv_bfloat16* __restrict__ Whi, const __nv_bfloat16* __restrict__ Wlo,
    int K, int m0, int n0, char* smem)
{
    int tid = threadIdx.x;
    int wid = tid >> 5;
    int wm = (wid >> 1) * 32;
    int wn = (wid & 1) * 64;
    uint32_t sbase = smem_u32(smem);

    wmma::fragment<wmma::accumulator, 16, 16, 16, float> acc[2][4];
#pragma unroll
    for (int i = 0; i < 2; i++)
#pragma unroll
        for (int j = 0; j < 4; j++) wmma::fill_fragment(acc[i][j], 0.0f);

    const int NK = K >> 5;
    stage_load<STEP>(Xhi, Xlo, Whi, Wlo, K, m0, n0, 0, sbase);

    for (int it = 0; it < NK; it++) {
        if (it + 1 < NK) {
            stage_load<STEP>(Xhi, Xlo, Whi, Wlo, K, m0, n0, (it + 1) << 5,
                             sbase + ((it + 1) & 1) * STG);
            asm volatile("cp.async.wait_group 1;" ::: "memory");
        } else {
            asm volatile("cp.async.wait_group 0;" ::: "memory");
        }
        __syncthreads();

        char* st = smem + (it & 1) * STG;
        __nv_bfloat16* sAhi = (__nv_bfloat16*)st;
        __nv_bfloat16* sAlo = sAhi + 128 * LDA;
        __nv_bfloat16* sBhi = sAlo + 128 * LDA;
        __nv_bfloat16* sBlo = sBhi + 128 * LDA;

#pragma unroll
        for (int kk = 0; kk < 32; kk += 16) {
            wmma::fragment<wmma::matrix_a, 16, 16, 16, __nv_bfloat16, wmma::row_major> ah[2], al[2];
#pragma unroll
            for (int i = 0; i < 2; i++) {
                wmma::load_matrix_sync(ah[i], sAhi + (wm + 16 * i) * LDA + kk, LDA);
                wmma::load_matrix_sync(al[i], sAlo + (wm + 16 * i) * LDA + kk, LDA);
            }
#pragma unroll
            for (int j = 0; j < 4; j++) {
                wmma::fragment<wmma::matrix_b, 16, 16, 16, __nv_bfloat16, wmma::col_major> bh, bl;
                wmma::load_matrix_sync(bh, sBhi + (wn + 16 * j) * LDA + kk, LDA);
                wmma::load_matrix_sync(bl, sBlo + (wn + 16 * j) * LDA + kk, LDA);
#pragma unroll
                for (int i = 0; i < 2; i++) {
                    wmma::mma_sync(acc[i][j], ah[i], bh, acc[i][j]);
                    wmma::mma_sync(acc[i][j], ah[i], bl, acc[i][j]);
                    wmma::mma_sync(acc[i][j], al[i], bh, acc[i][j]);
                }
            }
        }
        __syncthreads();
    }

    float* sC = (float*)smem;
#pragma unroll
    for (int i = 0; i < 2; i++)
#pragma unroll
        for (int j = 0; j < 4; j++)
            wmma::store_matrix_sync(sC + (wm + 16 * i) * LDC + wn + 16 * j, acc[i][j],
                                    LDC, wmma::mem_row_major);
    __syncthreads();
}

// ---------------- layer-1 input projection: xg = Y @ W^T + b1 + b2 ----------------
__global__ __launch_bounds__(256) void gemm_in_k(
    const __nv_bfloat16* __restrict__ Xhi, const __nv_bfloat16* __restrict__ Xlo,
    const __nv_bfloat16* __restrict__ Whi, const __nv_bfloat16* __restrict__ Wlo,
    const float* __restrict__ b1, const float* __restrict__ b2,
    float* __restrict__ C, int K)
{
    extern __shared__ char smem[];
    int m0 = blockIdx.y * 128, n0 = blockIdx.x * 128;
    gemm_core<0>(Xhi, Xlo, Whi, Wlo, K, m0, n0, smem);

    float* sC = (float*)smem;
    int tid = threadIdx.x;
    int col = tid & 127, half = tid >> 7;
    float bsum = b1[n0 + col] + b2[n0 + col];
#pragma unroll 4
    for (int rr = 0; rr < 64; rr++) {
        int r = half * 64 + rr;
        C[(size_t)(m0 + r) * G4 + n0 + col] = sC[r * LDC + col] + bsum;
    }
}

// ---------------- fused LSTM recurrent step ----------------
// TOK=1: layer-0, gate preacts gathered from 37-row table via token ids (exact fp32)
// TOK=0: layer-1, gate preacts read from xg
template<int TOK>
__global__ __launch_bounds__(256) void lstm_step_k(
    const __nv_bfloat16* __restrict__ hhi_c, const __nv_bfloat16* __restrict__ hlo_c,
    __nv_bfloat16* __restrict__ hhi_n, __nv_bfloat16* __restrict__ hlo_n,
    float* __restrict__ c_st,
    const __nv_bfloat16* __restrict__ Whi, const __nv_bfloat16* __restrict__ Wlo,
    const float* __restrict__ xg, const float* __restrict__ tab, const int* __restrict__ toks,
    float* __restrict__ y, __nv_bfloat16* __restrict__ yhi, __nv_bfloat16* __restrict__ ylo,
    int t)
{
    extern __shared__ char smem[];
    int m0 = blockIdx.y * 128, n0 = blockIdx.x * 32;
    gemm_core<1>(hhi_c, hlo_c, Whi, Wlo, HID, m0, n0, smem);

    float* sC = (float*)smem;
    int tid = threadIdx.x;
    int cc = tid & 31, msub = tid >> 5;
    int n = n0 + cc;
    int cl = (cc & 15) + ((cc >> 4) << 6);
#pragma unroll 4
    for (int rr = 0; rr < 16; rr++) {
        int r = msub * 16 + rr;
        int gm = m0 + r;
        float di = sC[r * LDC + cl];
        float df = sC[r * LDC + cl + 16];
        float dg = sC[r * LDC + cl + 32];
        float dv = sC[r * LDC + cl + 48];
        float x0, x1, x2, x3;
        if (TOK) {
            int tk = toks[gm * SEQ + t];
            const float* tb = tab + (size_t)tk * G4 + n;
            x0 = tb[0]; x1 = tb[HID]; x2 = tb[2 * HID]; x3 = tb[3 * HID];
        } else {
            size_t xb = ((size_t)gm * SEQ + t) * G4 + n;
            x0 = xg[xb]; x1 = xg[xb + HID]; x2 = xg[xb + 2 * HID]; x3 = xg[xb + 3 * HID];
        }
        float iv = sig_ (di + x0);
        float fv = sig_ (df + x1);
        float gv = tanh_(dg + x2);
        float ov = sig_ (dv + x3);
        size_t ci = (size_t)gm * HID + n;
        float cn = fv * c_st[ci] + iv * gv;
        c_st[ci] = cn;
        float h = ov * tanh_(cn);
        size_t yi = ((size_t)gm * SEQ + t) * HID + n;
        y[yi] = h;
        __nv_bfloat16 hh, hl;
        split2(h, hh, hl);
        hhi_n[ci] = hh; hlo_n[ci] = hl;
        yhi[yi] = hh;   ylo[yi] = hl;
    }
}

// ---------------- layer-0 gate table: tab[v][g] = emb[v]·W_ih0[g]^T + b1[g] + b2[g] ----
__global__ void tab_k(const float* __restrict__ emb, const float* __restrict__ W,
                      const float* __restrict__ b1, const float* __restrict__ b2,
                      float* __restrict__ tab)
{
    __shared__ float es[EMB];
    int v = blockIdx.x;
    int g = blockIdx.y * 256 + threadIdx.x;
    for (int k = threadIdx.x; k < EMB; k += 256) es[k] = emb[v * EMB + k];
    __syncthreads();
    const float* wr = W + (size_t)g * EMB;
    float acc = 0.0f;
#pragma unroll 8
    for (int k = 0; k < EMB; k++) acc += es[k] * wr[k];
    tab[v * G4 + g] = acc + b1[g] + b2[g];
}

__global__ void dtok_k(const int* __restrict__ tgt, int* __restrict__ dtok) {
    int i = blockIdx.x * 256 + threadIdx.x;
    if (i < MROWS) {
        int t = i % SEQ;
        dtok[i] = (t == 0) ? 1 : tgt[i - 1];   // [SOS, tgt[:, :-1]]
    }
}

// ---------------- small kernels ----------------
__global__ void zero_u4(uint4* __restrict__ p, int n) {
    int i = blockIdx.x * 256 + threadIdx.x;
    if (i < n) p[i] = make_uint4(0, 0, 0, 0);
}

__global__ void conv_k(const float* __restrict__ s, __nv_bfloat16* __restrict__ hi,
                       __nv_bfloat16* __restrict__ lo, int n) {
    int i = (blockIdx.x * 256 + threadIdx.x) * 4;
    if (i < n) {
        float4 v = *(const float4*)(s + i);
        __nv_bfloat16 h0, l0, h1, l1, h2, l2, h3, l3;
        split2(v.x, h0, l0); split2(v.y, h1, l1);
        split2(v.z, h2, l2); split2(v.w, h3, l3);
        __nv_bfloat162* ph = (__nv_bfloat162*)(hi + i);
        __nv_bfloat162* pl = (__nv_bfloat162*)(lo + i);
        ph[0] = __nv_bfloat162{h0, h1}; ph[1] = __nv_bfloat162{h2, h3};
        pl[0] = __nv_bfloat162{l0, l1}; pl[1] = __nv_bfloat162{l2, l3};
    }
}

__global__ __launch_bounds__(128) void fc_k(
    const float* __restrict__ Y, const float* __restrict__ W,
    const float* __restrict__ bias, float* __restrict__ out)
{
    __shared__ float As[128][33];
    __shared__ float Ws[32][40];
    int tid = threadIdx.x;
    int row0 = blockIdx.x * 128;

    float acc[VOC];
#pragma unroll
    for (int v = 0; v < VOC; v++) acc[v] = 0.0f;

    for (int k0 = 0; k0 < HID; k0 += 32) {
#pragma unroll
        for (int i = 0; i < 8; i++) {
            int f = i * 128 + tid;
            int r = f >> 3, k4 = f & 7;
            float4 v = *(const float4*)&Y[(size_t)(row0 + r) * HID + k0 + k4 * 4];
            As[r][k4 * 4 + 0] = v.x; As[r][k4 * 4 + 1] = v.y;
            As[r][k4 * 4 + 2] = v.z; As[r][k4 * 4 + 3] = v.w;
        }
        for (int l = tid; l < VOC * 32; l += 128) {
            int v = l >> 5, kk = l & 31;
            Ws[kk][v] = W[(size_t)v * HID + k0 + kk];
        }
        __syncthreads();
#pragma unroll
        for (int kk = 0; kk < 32; kk++) {
            float a = As[tid][kk];
#pragma unroll
            for (int v = 0; v < VOC; v++) acc[v] += a * Ws[kk][v];
        }
        __syncthreads();
    }
    int row = row0 + tid;
#pragma unroll
    for (int v = 0; v < VOC; v++)
        out[(size_t)row * VOC + v] = acc[v] + bias[v];
}

// ---------------- driver ----------------
extern "C" void kernel_launch(void* const* d_in, const int* in_sizes, int n_in,
                              void* d_out, int out_size)
{
    const int*   src    = (const int*)  d_in[0];
    const int*   tgt    = (const int*)  d_in[1];
    const float* emb    = (const float*)d_in[2];
    const float* eW_ih0 = (const float*)d_in[3];
    const float* eW_hh0 = (const float*)d_in[4];
    const float* eb_ih0 = (const float*)d_in[5];
    const float* eb_hh0 = (const float*)d_in[6];
    const float* eW_ih1 = (const float*)d_in[7];
    const float* eW_hh1 = (const float*)d_in[8];
    const float* eb_ih1 = (const float*)d_in[9];
    const float* eb_hh1 = (const float*)d_in[10];
    const float* dW_ih0 = (const float*)d_in[11];
    const float* dW_hh0 = (const float*)d_in[12];
    const float* db_ih0 = (const float*)d_in[13];
    const float* db_hh0 = (const float*)d_in[14];
    const float* dW_ih1 = (const float*)d_in[15];
    const float* dW_hh1 = (const float*)d_in[16];
    const float* db_ih1 = (const float*)d_in[17];
    const float* db_hh1 = (const float*)d_in[18];
    const float* fcW    = (const float*)d_in[19];
    const float* fcb    = (const float*)d_in[20];
    float* out = (float*)d_out;

    cudaFuncSetAttribute(gemm_in_k,      cudaFuncAttributeMaxDynamicSharedMemorySize, SMEM_ALLOC);
    cudaFuncSetAttribute(lstm_step_k<0>, cudaFuncAttributeMaxDynamicSharedMemorySize, SMEM_ALLOC);
    cudaFuncSetAttribute(lstm_step_k<1>, cudaFuncAttributeMaxDynamicSharedMemorySize, SMEM_ALLOC);

    float *xg, *y, *c0, *c1, *tabE, *tabD;
    int* dtok;
    __nv_bfloat16 *yhi, *ylo, *whi, *wlo;
    __nv_bfloat16 *h0hi_a, *h0lo_a, *h0hi_b, *h0lo_b, *h1hi_a, *h1lo_a, *h1hi_b, *h1lo_b;
    cudaGetSymbolAddress((void**)&xg,   g_xg);
    cudaGetSymbolAddress((void**)&y,    g_y);
    cudaGetSymbolAddress((void**)&yhi,  g_yhi);
    cudaGetSymbolAddress((void**)&ylo,  g_ylo);
    cudaGetSymbolAddress((void**)&whi,  g_whi);
    cudaGetSymbolAddress((void**)&wlo,  g_wlo);
    cudaGetSymbolAddress((void**)&tabE, g_tabE);
    cudaGetSymbolAddress((void**)&tabD, g_tabD);
    cudaGetSymbolAddress((void**)&dtok, g_dtok);
    cudaGetSymbolAddress((void**)&h0hi_a, g_h0hi_a);
    cudaGetSymbolAddress((void**)&h0lo_a, g_h0lo_a);
    cudaGetSymbolAddress((void**)&h0hi_b, g_h0hi_b);
    cudaGetSymbolAddress((void**)&h0lo_b, g_h0lo_b);
    cudaGetSymbolAddress((void**)&h1hi_a, g_h1hi_a);
    cudaGetSymbolAddress((void**)&h1lo_a, g_h1lo_a);
    cudaGetSymbolAddress((void**)&h1hi_b, g_h1hi_b);
    cudaGetSymbolAddress((void**)&h1lo_b, g_h1lo_b);
    cudaGetSymbolAddress((void**)&c0, g_c0);
    cudaGetSymbolAddress((void**)&c1, g_c1);

    const size_t WSLOT = (size_t)G4 * HID;

    // ---- weight conversion to split bf16 (6 slots) ----
    {
        int n2 = G4 * HID;
        int b2 = n2 / 1024;
        conv_k<<<b2, 256>>>(eW_hh0, whi + 0 * WSLOT, wlo + 0 * WSLOT, n2);
        conv_k<<<b2, 256>>>(eW_ih1, whi + 1 * WSLOT, wlo + 1 * WSLOT, n2);
        conv_k<<<b2, 256>>>(eW_hh1, whi + 2 * WSLOT, wlo + 2 * WSLOT, n2);
        conv_k<<<b2, 256>>>(dW_hh0, whi + 3 * WSLOT, wlo + 3 * WSLOT, n2);
        conv_k<<<b2, 256>>>(dW_ih1, whi + 4 * WSLOT, wlo + 4 * WSLOT, n2);
        conv_k<<<b2, 256>>>(dW_hh1, whi + 5 * WSLOT, wlo + 5 * WSLOT, n2);
    }
    // ---- layer-0 gate tables (exact fp32) + decoder tokens ----
    {
        dim3 tg(VOC, G4 / 256);
        tab_k<<<tg, 256>>>(emb, eW_ih0, eb_ih0, eb_hh0, tabE);
        tab_k<<<tg, 256>>>(emb, dW_ih0, db_ih0, db_hh0, tabD);
        dtok_k<<<(MROWS + 255) / 256, 256>>>(tgt, dtok);
    }
    // ---- zero initial states ----
    {
        int nb = BATCH * HID * 2 / 16;
        int nf = BATCH * HID * 4 / 16;
        zero_u4<<<(nb + 255) / 256, 256>>>((uint4*)h0hi_a, nb);
        zero_u4<<<(nb + 255) / 256, 256>>>((uint4*)h0lo_a, nb);
        zero_u4<<<(nb + 255) / 256, 256>>>((uint4*)h1hi_a, nb);
        zero_u4<<<(nb + 255) / 256, 256>>>((uint4*)h1lo_a, nb);
        zero_u4<<<(nf + 255) / 256, 256>>>((uint4*)c0, nf);
        zero_u4<<<(nf + 255) / 256, 256>>>((uint4*)c1, nf);
    }

    dim3 ggrid(G4 / 128, MROWS / 128);   // (32, 384)
    dim3 sgrid(HID / 32, BATCH / 128);   // (32, 16)

    __nv_bfloat16 *hc0h = h0hi_a, *hc0l = h0lo_a, *hn0h = h0hi_b, *hn0l = h0lo_b;
    __nv_bfloat16 *hc1h = h1hi_a, *hc1l = h1lo_a, *hn1h = h1hi_b, *hn1l = h1lo_b;

    // ---- encoder layer 0 (table path, no input GEMM) ----
    for (int t = 0; t < SEQ; t++) {
        lstm_step_k<1><<<sgrid, 256, SMEM_ALLOC>>>(hc0h, hc0l, hn0h, hn0l, c0,
                                                   whi + 0 * WSLOT, wlo + 0 * WSLOT,
                                                   (const float*)nullptr, tabE, src,
                                                   y, yhi, ylo, t);
        __nv_bfloat16* t1 = hc0h; hc0h = hn0h; hn0h = t1;
        __nv_bfloat16* t2 = hc0l; hc0l = hn0l; hn0l = t2;
    }
    // ---- encoder layer 1 ----
    gemm_in_k<<<ggrid, 256, SMEM_ALLOC>>>(yhi, ylo, whi + 1 * WSLOT, wlo + 1 * WSLOT,
                                          eb_ih1, eb_hh1, xg, HID);
    for (int t = 0; t < SEQ; t++) {
        lstm_step_k<0><<<sgrid, 256, SMEM_ALLOC>>>(hc1h, hc1l, hn1h, hn1l, c1,
                                                   whi + 2 * WSLOT, wlo + 2 * WSLOT,
                                                   xg, (const float*)nullptr, (const int*)nullptr,
                                                   y, yhi, ylo, t);
        __nv_bfloat16* t1 = hc1h; hc1h = hn1h; hn1h = t1;
        __nv_bfloat16* t2 = hc1l; hc1l = hn1l; hn1l = t2;
    }
    // ---- decoder layer 0 (table path; states carry over) ----
    for (int t = 0; t < SEQ; t++) {
        lstm_step_k<1><<<sgrid, 256, SMEM_ALLOC>>>(hc0h, hc0l, hn0h, hn0l, c0,
                                                   whi + 3 * WSLOT, wlo + 3 * WSLOT,
                                                   (const float*)nullptr, tabD, dtok,
                                                   y, yhi, ylo, t);
        __nv_bfloat16* t1 = hc0h; hc0h = hn0h; hn0h = t1;
        __nv_bfloat16* t2 = hc0l; hc0l = hn0l; hn0l = t2;
    }
    // ---- decoder layer 1 ----
    gemm_in_k<<<ggrid, 256, SMEM_ALLOC>>>(yhi, ylo, whi + 4 * WSLOT, wlo + 4 * WSLOT,
                                          db_ih1, db_hh1, xg, HID);
    for (int t = 0; t < SEQ; t++) {
        lstm_step_k<0><<<sgrid, 256, SMEM_ALLOC>>>(hc1h, hc1l, hn1h, hn1l, c1,
                                                   whi + 5 * WSLOT, wlo + 5 * WSLOT,
                                                   xg, (const float*)nullptr, (const int*)nullptr,
                                                   y, yhi, ylo, t);
        __nv_bfloat16* t1 = hc1h; hc1h = hn1h; hn1h = t1;
        __nv_bfloat16* t2 = hc1l; hc1l = hn1l; hn1l = t2;
    }
    // ---- output projection ----
    fc_k<<<MROWS / 128, 128>>>(y, fcW, fcb, out);
}

// round 6
// speedup vs baseline: 3.4558x; 1.7267x over previous
#include <cuda_runtime.h>
#include <cuda_fp16.h>
#include <mma.h>
#include <cstdint>
#include <math.h>

using namespace nvcuda;

// Problem constants
#define BATCH 2048
#define SEQ   24
#define EMB   256
#define HID   1024
#define VOC   37
#define G4    4096
#define MROWS (BATCH*SEQ)   // 49152

#define LDA 40              // stage leading dim (fp16): 80B rows
#define LDC 132             // epilogue C leading dim (floats)
#define ARRB (128*LDA*2)    // 10240 bytes per matrix per stage
#define STG  (3*ARRB)       // 30720 bytes per stage (Ahi, Alo, B)
#define NSTAGE 3
#define SMEM_ALLOC (NSTAGE*STG)   // 92160 >= epilogue sC (67584)

// ---------------- device scratch ----------------
__device__ float g_xg[(size_t)MROWS * G4];        // gate preactivations (layer-1 passes)
__device__ __half g_yhi[(size_t)MROWS * HID];     // layer outputs, split fp16
__device__ __half g_ylo[(size_t)MROWS * HID];
__device__ __half g_w[(size_t)6 * G4 * HID];      // weights, single fp16 (hh0e,ih1e,hh1e,hh0d,ih1d,hh1d)
__device__ float g_tabE[VOC * G4];                // layer-0 gate tables (exact fp32)
__device__ float g_tabD[VOC * G4];
__device__ int   g_dtok[MROWS];                   // decoder input tokens
__device__ __half g_h0hi_a[BATCH*HID], g_h0lo_a[BATCH*HID];
__device__ __half g_h0hi_b[BATCH*HID], g_h0lo_b[BATCH*HID];
__device__ __half g_h1hi_a[BATCH*HID], g_h1lo_a[BATCH*HID];
__device__ __half g_h1hi_b[BATCH*HID], g_h1lo_b[BATCH*HID];
__device__ float g_c0[BATCH*HID], g_c1[BATCH*HID];

// ---------------- helpers ----------------
__device__ __forceinline__ float sig_(float x)  { return 1.0f / (1.0f + __expf(-x)); }
__device__ __forceinline__ float tanh_(float x) { float t = __expf(2.0f * x); return 1.0f - 2.0f / (t + 1.0f); }

__device__ __forceinline__ void split2h(float v, __half& hi, __half& lo) {
    hi = __float2half_rn(v);
    lo = __float2half_rn(v - __half2float(hi));
}

__device__ __forceinline__ uint32_t smem_u32(const void* p) {
    uint32_t a;
    asm("{ .reg .u64 t; cvta.to.shared.u64 t, %1; cvt.u32.u64 %0, t; }" : "=r"(a) : "l"(p));
    return a;
}

__device__ __forceinline__ void cpa16(uint32_t dst, const void* src) {
    asm volatile("cp.async.cg.shared.global [%0], [%1], 16;" :: "r"(dst), "l"(src) : "memory");
}

// ---------------- stage loader (cp.async): Ahi, Alo, B(single) ----------------
// STEP=1 (lstm): B tile row r -> W row gate*HID + n0 + cc, gate=(r>>4)&3, cc=(r&15)|(((r>>6)&1)<<4)
// STEP=0 (proj): B tile row r -> W row n0 + r
template<int STEP>
__device__ __forceinline__ void stage_load(
    const __half* __restrict__ Xhi, const __half* __restrict__ Xlo,
    const __half* __restrict__ W,
    int K, int m0, int n0, int k0, uint32_t sbase)
{
    int tid = threadIdx.x;
#pragma unroll
    for (int i = 0; i < 6; i++) {
        int idx = tid + (i << 8);     // 0..1535
        int arr = idx >> 9;           // 0 Ahi, 1 Alo, 2 B
        int r   = (idx >> 2) & 127;
        int c   = idx & 3;            // 16B chunk within 64B row
        const __half* src;
        if (arr == 0)      src = Xhi + (size_t)(m0 + r) * K + k0 + (c << 3);
        else if (arr == 1) src = Xlo + (size_t)(m0 + r) * K + k0 + (c << 3);
        else {
            int wrow;
            if (STEP) { int g = (r >> 4) & 3; int cc = (r & 15) | (((r >> 6) & 1) << 4); wrow = g * HID + n0 + cc; }
            else      { wrow = n0 + r; }
            src = W + (size_t)wrow * K + k0 + (c << 3);
        }
        uint32_t dst = sbase + arr * ARRB + r * (LDA * 2) + (c << 4);
        cpa16(dst, src);
    }
    asm volatile("cp.async.commit_group;" ::: "memory");
}

// ---------------- 2-pass split-fp16 GEMM core (3-stage pipeline) ----------------
// 128x128 tile of X[M,K] @ W[.,K]^T, fp32 result staged into sC (reuses smem).
template<int STEP>
__device__ __forceinline__ void gemm_core(
    const __half* __restrict__ Xhi, const __half* __restrict__ Xlo,
    const __half* __restrict__ W,
    int K, int m0, int n0, char* smem)
{
    int tid = threadIdx.x;
    int wid = tid >> 5;
    int wm = (wid >> 1) * 32;
    int wn = (wid & 1) * 64;
    uint32_t sbase = smem_u32(smem);

    wmma::fragment<wmma::accumulator, 16, 16, 16, float> acc[2][4];
#pragma unroll
    for (int i = 0; i < 2; i++)
#pragma unroll
        for (int j = 0; j < 4; j++) wmma::fill_fragment(acc[i][j], 0.0f);

    const int NK = K >> 5;
    stage_load<STEP>(Xhi, Xlo, W, K, m0, n0, 0, sbase);
    stage_load<STEP>(Xhi, Xlo, W, K, m0, n0, 32, sbase + STG);

    for (int it = 0; it < NK; it++) {
        if (it + 2 < NK) {
            int nx = it + 2;
            stage_load<STEP>(Xhi, Xlo, W, K, m0, n0, nx << 5, sbase + (nx % NSTAGE) * STG);
            asm volatile("cp.async.wait_group 2;" ::: "memory");
        } else if (it + 1 < NK) {
            asm volatile("cp.async.wait_group 1;" ::: "memory");
        } else {
            asm volatile("cp.async.wait_group 0;" ::: "memory");
        }
        __syncthreads();

        char* st = smem + (it % NSTAGE) * STG;
        __half* sAhi = (__half*)st;
        __half* sAlo = sAhi + 128 * LDA;
        __half* sB   = sAlo + 128 * LDA;

#pragma unroll
        for (int kk = 0; kk < 32; kk += 16) {
            wmma::fragment<wmma::matrix_a, 16, 16, 16, __half, wmma::row_major> ah[2], al[2];
#pragma unroll
            for (int i = 0; i < 2; i++) {
                wmma::load_matrix_sync(ah[i], sAhi + (wm + 16 * i) * LDA + kk, LDA);
                wmma::load_matrix_sync(al[i], sAlo + (wm + 16 * i) * LDA + kk, LDA);
            }
#pragma unroll
            for (int j = 0; j < 4; j++) {
                wmma::fragment<wmma::matrix_b, 16, 16, 16, __half, wmma::col_major> b;
                wmma::load_matrix_sync(b, sB + (wn + 16 * j) * LDA + kk, LDA);
#pragma unroll
                for (int i = 0; i < 2; i++) {
                    wmma::mma_sync(acc[i][j], ah[i], b, acc[i][j]);
                    wmma::mma_sync(acc[i][j], al[i], b, acc[i][j]);
                }
            }
        }
        __syncthreads();
    }

    float* sC = (float*)smem;
#pragma unroll
    for (int i = 0; i < 2; i++)
#pragma unroll
        for (int j = 0; j < 4; j++)
            wmma::store_matrix_sync(sC + (wm + 16 * i) * LDC + wn + 16 * j, acc[i][j],
                                    LDC, wmma::mem_row_major);
    __syncthreads();
}

// ---------------- layer-1 input projection: xg = Y @ W^T + b1 + b2 ----------------
__global__ __launch_bounds__(256) void gemm_in_k(
    const __half* __restrict__ Xhi, const __half* __restrict__ Xlo,
    const __half* __restrict__ W,
    const float* __restrict__ b1, const float* __restrict__ b2,
    float* __restrict__ C, int K)
{
    extern __shared__ char smem[];
    int m0 = blockIdx.y * 128, n0 = blockIdx.x * 128;
    gemm_core<0>(Xhi, Xlo, W, K, m0, n0, smem);

    float* sC = (float*)smem;
    int tid = threadIdx.x;
    int col = tid & 127, half_ = tid >> 7;
    float bsum = b1[n0 + col] + b2[n0 + col];
#pragma unroll 4
    for (int rr = 0; rr < 64; rr++) {
        int r = half_ * 64 + rr;
        C[(size_t)(m0 + r) * G4 + n0 + col] = sC[r * LDC + col] + bsum;
    }
}

// ---------------- fused LSTM recurrent step ----------------
// TOK=1: layer-0, gate preacts gathered from 37-row table via token ids (exact fp32)
// TOK=0: layer-1, gate preacts read from xg
template<int TOK>
__global__ __launch_bounds__(256) void lstm_step_k(
    const __half* __restrict__ hhi_c, const __half* __restrict__ hlo_c,
    __half* __restrict__ hhi_n, __half* __restrict__ hlo_n,
    float* __restrict__ c_st,
    const __half* __restrict__ W,
    const float* __restrict__ xg, const float* __restrict__ tab, const int* __restrict__ toks,
    __half* __restrict__ yhi, __half* __restrict__ ylo,
    int t)
{
    extern __shared__ char smem[];
    int m0 = blockIdx.y * 128, n0 = blockIdx.x * 32;
    gemm_core<1>(hhi_c, hlo_c, W, HID, m0, n0, smem);

    float* sC = (float*)smem;
    int tid = threadIdx.x;
    int cc = tid & 31, msub = tid >> 5;
    int n = n0 + cc;
    int cl = (cc & 15) + ((cc >> 4) << 6);
#pragma unroll 4
    for (int rr = 0; rr < 16; rr++) {
        int r = msub * 16 + rr;
        int gm = m0 + r;
        float di = sC[r * LDC + cl];
        float df = sC[r * LDC + cl + 16];
        float dg = sC[r * LDC + cl + 32];
        float dv = sC[r * LDC + cl + 48];
        float x0, x1, x2, x3;
        if (TOK) {
            int tk = toks[gm * SEQ + t];
            const float* tb = tab + (size_t)tk * G4 + n;
            x0 = tb[0]; x1 = tb[HID]; x2 = tb[2 * HID]; x3 = tb[3 * HID];
        } else {
            size_t xb = ((size_t)gm * SEQ + t) * G4 + n;
            x0 = xg[xb]; x1 = xg[xb + HID]; x2 = xg[xb + 2 * HID]; x3 = xg[xb + 3 * HID];
        }
        float iv = sig_ (di + x0);
        float fv = sig_ (df + x1);
        float gv = tanh_(dg + x2);
        float ov = sig_ (dv + x3);
        size_t ci = (size_t)gm * HID + n;
        float cn = fv * c_st[ci] + iv * gv;
        c_st[ci] = cn;
        float h = ov * tanh_(cn);
        __half hh, hl;
        split2h(h, hh, hl);
        hhi_n[ci] = hh; hlo_n[ci] = hl;
        size_t yi = ((size_t)gm * SEQ + t) * HID + n;
        yhi[yi] = hh;   ylo[yi] = hl;
    }
}

// ---------------- layer-0 gate table: tab[v][g] = emb[v]·W_ih0[g]^T + b1[g] + b2[g] ----
__global__ void tab_k(const float* __restrict__ emb, const float* __restrict__ W,
                      const float* __restrict__ b1, const float* __restrict__ b2,
                      float* __restrict__ tab)
{
    __shared__ float es[EMB];
    int v = blockIdx.x;
    int g = blockIdx.y * 256 + threadIdx.x;
    for (int k = threadIdx.x; k < EMB; k += 256) es[k] = emb[v * EMB + k];
    __syncthreads();
    const float* wr = W + (size_t)g * EMB;
    float acc = 0.0f;
#pragma unroll 8
    for (int k = 0; k < EMB; k++) acc += es[k] * wr[k];
    tab[v * G4 + g] = acc + b1[g] + b2[g];
}

__global__ void dtok_k(const int* __restrict__ tgt, int* __restrict__ dtok) {
    int i = blockIdx.x * 256 + threadIdx.x;
    if (i < MROWS) {
        int t = i % SEQ;
        dtok[i] = (t == 0) ? 1 : tgt[i - 1];   // [SOS, tgt[:, :-1]]
    }
}

// ---------------- small kernels ----------------
__global__ void zero_u4(uint4* __restrict__ p, int n) {
    int i = blockIdx.x * 256 + threadIdx.x;
    if (i < n) p[i] = make_uint4(0, 0, 0, 0);
}

__global__ void convh_k(const float* __restrict__ s, __half* __restrict__ w, int n) {
    int i = (blockIdx.x * 256 + threadIdx.x) * 4;
    if (i < n) {
        float4 v = *(const float4*)(s + i);
        __half2* p = (__half2*)(w + i);
        p[0] = __floats2half2_rn(v.x, v.y);
        p[1] = __floats2half2_rn(v.z, v.w);
    }
}

// ---------------- final projection: out = (Yhi+Ylo) @ fcW^T + fcb ----------------
__global__ __launch_bounds__(128) void fc_k(
    const __half* __restrict__ Yhi, const __half* __restrict__ Ylo,
    const float* __restrict__ W, const float* __restrict__ bias, float* __restrict__ out)
{
    __shared__ float As[128][33];
    __shared__ float Ws[32][40];
    int tid = threadIdx.x;
    int row0 = blockIdx.x * 128;

    float acc[VOC];
#pragma unroll
    for (int v = 0; v < VOC; v++) acc[v] = 0.0f;

    for (int k0 = 0; k0 < HID; k0 += 32) {
#pragma unroll
        for (int i = 0; i < 8; i++) {
            int f = i * 128 + tid;     // 1024 quads of 4 halves
            int r = f >> 3, q = f & 7;
            const __half2* ph = (const __half2*)&Yhi[(size_t)(row0 + r) * HID + k0 + q * 4];
            const __half2* pl = (const __half2*)&Ylo[(size_t)(row0 + r) * HID + k0 + q * 4];
            float2 h0 = __half22float2(ph[0]), h1 = __half22float2(ph[1]);
            float2 l0 = __half22float2(pl[0]), l1 = __half22float2(pl[1]);
            As[r][q * 4 + 0] = h0.x + l0.x; As[r][q * 4 + 1] = h0.y + l0.y;
            As[r][q * 4 + 2] = h1.x + l1.x; As[r][q * 4 + 3] = h1.y + l1.y;
        }
        for (int l = tid; l < VOC * 32; l += 128) {
            int v = l >> 5, kk = l & 31;
            Ws[kk][v] = W[(size_t)v * HID + k0 + kk];
        }
        __syncthreads();
#pragma unroll
        for (int kk = 0; kk < 32; kk++) {
            float a = As[tid][kk];
#pragma unroll
            for (int v = 0; v < VOC; v++) acc[v] += a * Ws[kk][v];
        }
        __syncthreads();
    }
    int row = row0 + tid;
#pragma unroll
    for (int v = 0; v < VOC; v++)
        out[(size_t)row * VOC + v] = acc[v] + bias[v];
}

// ---------------- driver ----------------
extern "C" void kernel_launch(void* const* d_in, const int* in_sizes, int n_in,
                              void* d_out, int out_size)
{
    const int*   src    = (const int*)  d_in[0];
    const int*   tgt    = (const int*)  d_in[1];
    const float* emb    = (const float*)d_in[2];
    const float* eW_ih0 = (const float*)d_in[3];
    const float* eW_hh0 = (const float*)d_in[4];
    const float* eb_ih0 = (const float*)d_in[5];
    const float* eb_hh0 = (const float*)d_in[6];
    const float* eW_ih1 = (const float*)d_in[7];
    const float* eW_hh1 = (const float*)d_in[8];
    const float* eb_ih1 = (const float*)d_in[9];
    const float* eb_hh1 = (const float*)d_in[10];
    const float* dW_ih0 = (const float*)d_in[11];
    const float* dW_hh0 = (const float*)d_in[12];
    const float* db_ih0 = (const float*)d_in[13];
    const float* db_hh0 = (const float*)d_in[14];
    const float* dW_ih1 = (const float*)d_in[15];
    const float* dW_hh1 = (const float*)d_in[16];
    const float* db_ih1 = (const float*)d_in[17];
    const float* db_hh1 = (const float*)d_in[18];
    const float* fcW    = (const float*)d_in[19];
    const float* fcb    = (const float*)d_in[20];
    float* out = (float*)d_out;

    cudaFuncSetAttribute(gemm_in_k,      cudaFuncAttributeMaxDynamicSharedMemorySize, SMEM_ALLOC);
    cudaFuncSetAttribute(lstm_step_k<0>, cudaFuncAttributeMaxDynamicSharedMemorySize, SMEM_ALLOC);
    cudaFuncSetAttribute(lstm_step_k<1>, cudaFuncAttributeMaxDynamicSharedMemorySize, SMEM_ALLOC);

    float *xg, *c0, *c1, *tabE, *tabD;
    int* dtok;
    __half *yhi, *ylo, *w;
    __half *h0hi_a, *h0lo_a, *h0hi_b, *h0lo_b, *h1hi_a, *h1lo_a, *h1hi_b, *h1lo_b;
    cudaGetSymbolAddress((void**)&xg,   g_xg);
    cudaGetSymbolAddress((void**)&yhi,  g_yhi);
    cudaGetSymbolAddress((void**)&ylo,  g_ylo);
    cudaGetSymbolAddress((void**)&w,    g_w);
    cudaGetSymbolAddress((void**)&tabE, g_tabE);
    cudaGetSymbolAddress((void**)&tabD, g_tabD);
    cudaGetSymbolAddress((void**)&dtok, g_dtok);
    cudaGetSymbolAddress((void**)&h0hi_a, g_h0hi_a);
    cudaGetSymbolAddress((void**)&h0lo_a, g_h0lo_a);
    cudaGetSymbolAddress((void**)&h0hi_b, g_h0hi_b);
    cudaGetSymbolAddress((void**)&h0lo_b, g_h0lo_b);
    cudaGetSymbolAddress((void**)&h1hi_a, g_h1hi_a);
    cudaGetSymbolAddress((void**)&h1lo_a, g_h1lo_a);
    cudaGetSymbolAddress((void**)&h1hi_b, g_h1hi_b);
    cudaGetSymbolAddress((void**)&h1lo_b, g_h1lo_b);
    cudaGetSymbolAddress((void**)&c0, g_c0);
    cudaGetSymbolAddress((void**)&c1, g_c1);

    const size_t WSLOT = (size_t)G4 * HID;

    // ---- weight conversion to fp16 (6 slots) ----
    {
        int n2 = G4 * HID;
        int b2 = n2 / 1024;
        convh_k<<<b2, 256>>>(eW_hh0, w + 0 * WSLOT, n2);
        convh_k<<<b2, 256>>>(eW_ih1, w + 1 * WSLOT, n2);
        convh_k<<<b2, 256>>>(eW_hh1, w + 2 * WSLOT, n2);
        convh_k<<<b2, 256>>>(dW_hh0, w + 3 * WSLOT, n2);
        convh_k<<<b2, 256>>>(dW_ih1, w + 4 * WSLOT, n2);
        convh_k<<<b2, 256>>>(dW_hh1, w + 5 * WSLOT, n2);
    }
    // ---- layer-0 gate tables (exact fp32) + decoder tokens ----
    {
        dim3 tg(VOC, G4 / 256);
        tab_k<<<tg, 256>>>(emb, eW_ih0, eb_ih0, eb_hh0, tabE);
        tab_k<<<tg, 256>>>(emb, dW_ih0, db_ih0, db_hh0, tabD);
        dtok_k<<<(MROWS + 255) / 256, 256>>>(tgt, dtok);
    }
    // ---- zero initial states ----
    {
        int nb = BATCH * HID * 2 / 16;   // fp16 arrays in uint4 units
        int nf = BATCH * HID * 4 / 16;   // fp32 arrays in uint4 units
        zero_u4<<<(nb + 255) / 256, 256>>>((uint4*)h0hi_a, nb);
        zero_u4<<<(nb + 255) / 256, 256>>>((uint4*)h0lo_a, nb);
        zero_u4<<<(nb + 255) / 256, 256>>>((uint4*)h1hi_a, nb);
        zero_u4<<<(nb + 255) / 256, 256>>>((uint4*)h1lo_a, nb);
        zero_u4<<<(nf + 255) / 256, 256>>>((uint4*)c0, nf);
        zero_u4<<<(nf + 255) / 256, 256>>>((uint4*)c1, nf);
    }

    dim3 ggrid(G4 / 128, MROWS / 128);   // (32, 384)
    dim3 sgrid(HID / 32, BATCH / 128);   // (32, 16)

    __half *hc0h = h0hi_a, *hc0l = h0lo_a, *hn0h = h0hi_b, *hn0l = h0lo_b;
    __half *hc1h = h1hi_a, *hc1l = h1lo_a, *hn1h = h1hi_b, *hn1l = h1lo_b;

    // ---- encoder layer 0 (table path, no input GEMM) ----
    for (int t = 0; t < SEQ; t++) {
        lstm_step_k<1><<<sgrid, 256, SMEM_ALLOC>>>(hc0h, hc0l, hn0h, hn0l, c0,
                                                   w + 0 * WSLOT,
                                                   (const float*)nullptr, tabE, src,
                                                   yhi, ylo, t);
        __half* t1 = hc0h; hc0h = hn0h; hn0h = t1;
        __half* t2 = hc0l; hc0l = hn0l; hn0l = t2;
    }
    // ---- encoder layer 1 ----
    gemm_in_k<<<ggrid, 256, SMEM_ALLOC>>>(yhi, ylo, w + 1 * WSLOT, eb_ih1, eb_hh1, xg, HID);
    for (int t = 0; t < SEQ; t++) {
        lstm_step_k<0><<<sgrid, 256, SMEM_ALLOC>>>(hc1h, hc1l, hn1h, hn1l, c1,
                                                   w + 2 * WSLOT,
                                                   xg, (const float*)nullptr, (const int*)nullptr,
                                                   yhi, ylo, t);
        __half* t1 = hc1h; hc1h = hn1h; hn1h = t1;
        __half* t2 = hc1l; hc1l = hn1l; hn1l = t2;
    }
    // ---- decoder layer 0 (table path; states carry over) ----
    for (int t = 0; t < SEQ; t++) {
        lstm_step_k<1><<<sgrid, 256, SMEM_ALLOC>>>(hc0h, hc0l, hn0h, hn0l, c0,
                                                   w + 3 * WSLOT,
                                                   (const float*)nullptr, tabD, dtok,
                                                   yhi, ylo, t);
        __half* t1 = hc0h; hc0h = hn0h; hn0h = t1;
        __half* t2 = hc0l; hc0l = hn0l; hn0l = t2;
    }
    // ---- decoder layer 1 ----
    gemm_in_k<<<ggrid, 256, SMEM_ALLOC>>>(yhi, ylo, w + 4 * WSLOT, db_ih1, db_hh1, xg, HID);
    for (int t = 0; t < SEQ; t++) {
        lstm_step_k<0><<<sgrid, 256, SMEM_ALLOC>>>(hc1h, hc1l, hn1h, hn1l, c1,
                                                   w + 5 * WSLOT,
                                                   xg, (const float*)nullptr, (const int*)nullptr,
                                                   yhi, ylo, t);
        __half* t1 = hc1h; hc1h = hn1h; hn1h = t1;
        __half* t2 = hc1l; hc1l = hn1l; hn1l = t2;
    }
    // ---- output projection ----
    fc_k<<<MROWS / 128, 128>>>(yhi, ylo, fcW, fcb, out);
}

// round 7
// speedup vs baseline: 3.8189x; 1.1051x over previous
#include <cuda_runtime.h>
#include <cuda_fp16.h>
#include <mma.h>
#include <cstdint>
#include <math.h>

using namespace nvcuda;

// Problem constants
#define BATCH 2048
#define SEQ   24
#define EMB   256
#define HID   1024
#define VOC   37
#define G4    4096
#define MROWS (BATCH*SEQ)   // 49152

#define LDA 40              // stage leading dim (fp16): 80B rows
#define LDC 132             // epilogue C leading dim (floats)
#define ARRB (128*LDA*2)    // 10240 bytes per matrix per stage
#define STG  (3*ARRB)       // 30720 bytes per stage (Ahi, Alo, B)
#define NSTAGE 3
#define SMEM_ALLOC (NSTAGE*STG)   // 92160 >= epilogue sC (67584); 2 CTA/SM fits 228KB

// ---------------- device scratch ----------------
__device__ float g_xg[(size_t)MROWS * G4];        // gate preactivations (layer-1 passes)
__device__ __half g_yhi[(size_t)MROWS * HID];     // layer outputs, split fp16
__device__ __half g_ylo[(size_t)MROWS * HID];
__device__ __half g_w[(size_t)6 * G4 * HID];      // weights fp16 (hh0e,ih1e,hh1e,hh0d,ih1d,hh1d)
__device__ float g_tabE[VOC * G4];                // layer-0 gate tables (exact fp32)
__device__ float g_tabD[VOC * G4];
__device__ int   g_dtok[MROWS];                   // decoder input tokens
__device__ __half g_h0hi_a[BATCH*HID], g_h0lo_a[BATCH*HID];
__device__ __half g_h0hi_b[BATCH*HID], g_h0lo_b[BATCH*HID];
__device__ __half g_h1hi_a[BATCH*HID], g_h1lo_a[BATCH*HID];
__device__ __half g_h1hi_b[BATCH*HID], g_h1lo_b[BATCH*HID];
__device__ float g_c0[BATCH*HID], g_c1[BATCH*HID];

// ---------------- helpers ----------------
__device__ __forceinline__ float sig_(float x)  { return 1.0f / (1.0f + __expf(-x)); }
__device__ __forceinline__ float tanh_(float x) { float t = __expf(2.0f * x); return 1.0f - 2.0f / (t + 1.0f); }

__device__ __forceinline__ void split2h(float v, __half& hi, __half& lo) {
    hi = __float2half_rn(v);
    lo = __float2half_rn(v - __half2float(hi));
}

__device__ __forceinline__ uint32_t smem_u32(const void* p) {
    uint32_t a;
    asm("{ .reg .u64 t; cvta.to.shared.u64 t, %1; cvt.u32.u64 %0, t; }" : "=r"(a) : "l"(p));
    return a;
}

__device__ __forceinline__ void cpa16(uint32_t dst, const void* src) {
    asm volatile("cp.async.cg.shared.global [%0], [%1], 16;" :: "r"(dst), "l"(src) : "memory");
}

// ---------------- stage loader (cp.async): Ahi, Alo, B(single) ----------------
template<int STEP>
__device__ __forceinline__ void stage_load(
    const __half* __restrict__ Xhi, const __half* __restrict__ Xlo,
    const __half* __restrict__ W,
    int K, int m0, int n0, int k0, uint32_t sbase)
{
    int tid = threadIdx.x;
#pragma unroll
    for (int i = 0; i < 6; i++) {
        int idx = tid + (i << 8);     // 0..1535
        int arr = idx >> 9;           // 0 Ahi, 1 Alo, 2 B
        int r   = (idx >> 2) & 127;
        int c   = idx & 3;            // 16B chunk within 64B row
        const __half* src;
        if (arr == 0)      src = Xhi + (size_t)(m0 + r) * K + k0 + (c << 3);
        else if (arr == 1) src = Xlo + (size_t)(m0 + r) * K + k0 + (c << 3);
        else {
            int wrow;
            if (STEP) { int g = (r >> 4) & 3; int cc = (r & 15) | (((r >> 6) & 1) << 4); wrow = g * HID + n0 + cc; }
            else      { wrow = n0 + r; }
            src = W + (size_t)wrow * K + k0 + (c << 3);
        }
        uint32_t dst = sbase + arr * ARRB + r * (LDA * 2) + (c << 4);
        cpa16(dst, src);
    }
    asm volatile("cp.async.commit_group;" ::: "memory");
}

// ---------------- 2-pass split-fp16 GEMM core (3-stage pipeline) ----------------
template<int STEP>
__device__ __forceinline__ void gemm_core(
    const __half* __restrict__ Xhi, const __half* __restrict__ Xlo,
    const __half* __restrict__ W,
    int K, int m0, int n0, char* smem)
{
    int tid = threadIdx.x;
    int wid = tid >> 5;
    int wm = (wid >> 1) * 32;
    int wn = (wid & 1) * 64;
    uint32_t sbase = smem_u32(smem);

    wmma::fragment<wmma::accumulator, 16, 16, 16, float> acc[2][4];
#pragma unroll
    for (int i = 0; i < 2; i++)
#pragma unroll
        for (int j = 0; j < 4; j++) wmma::fill_fragment(acc[i][j], 0.0f);

    const int NK = K >> 5;
    stage_load<STEP>(Xhi, Xlo, W, K, m0, n0, 0, sbase);
    stage_load<STEP>(Xhi, Xlo, W, K, m0, n0, 32, sbase + STG);

    for (int it = 0; it < NK; it++) {
        if (it + 2 < NK) {
            int nx = it + 2;
            stage_load<STEP>(Xhi, Xlo, W, K, m0, n0, nx << 5, sbase + (nx % NSTAGE) * STG);
            asm volatile("cp.async.wait_group 2;" ::: "memory");
        } else if (it + 1 < NK) {
            asm volatile("cp.async.wait_group 1;" ::: "memory");
        } else {
            asm volatile("cp.async.wait_group 0;" ::: "memory");
        }
        __syncthreads();

        char* st = smem + (it % NSTAGE) * STG;
        __half* sAhi = (__half*)st;
        __half* sAlo = sAhi + 128 * LDA;
        __half* sB   = sAlo + 128 * LDA;

#pragma unroll
        for (int kk = 0; kk < 32; kk += 16) {
            wmma::fragment<wmma::matrix_a, 16, 16, 16, __half, wmma::row_major> ah[2], al[2];
#pragma unroll
            for (int i = 0; i < 2; i++) {
                wmma::load_matrix_sync(ah[i], sAhi + (wm + 16 * i) * LDA + kk, LDA);
                wmma::load_matrix_sync(al[i], sAlo + (wm + 16 * i) * LDA + kk, LDA);
            }
#pragma unroll
            for (int j = 0; j < 4; j++) {
                wmma::fragment<wmma::matrix_b, 16, 16, 16, __half, wmma::col_major> b;
                wmma::load_matrix_sync(b, sB + (wn + 16 * j) * LDA + kk, LDA);
#pragma unroll
                for (int i = 0; i < 2; i++) {
                    wmma::mma_sync(acc[i][j], ah[i], b, acc[i][j]);
                    wmma::mma_sync(acc[i][j], al[i], b, acc[i][j]);
                }
            }
        }
        __syncthreads();
    }

    float* sC = (float*)smem;
#pragma unroll
    for (int i = 0; i < 2; i++)
#pragma unroll
        for (int j = 0; j < 4; j++)
            wmma::store_matrix_sync(sC + (wm + 16 * i) * LDC + wn + 16 * j, acc[i][j],
                                    LDC, wmma::mem_row_major);
    __syncthreads();
}

// ---------------- layer-1 input projection: xg = Y @ W^T + b1 + b2 ----------------
__global__ __launch_bounds__(256, 2) void gemm_in_k(
    const __half* __restrict__ Xhi, const __half* __restrict__ Xlo,
    const __half* __restrict__ W,
    const float* __restrict__ b1, const float* __restrict__ b2,
    float* __restrict__ C, int K)
{
    extern __shared__ char smem[];
    int m0 = blockIdx.y * 128, n0 = blockIdx.x * 128;
    gemm_core<0>(Xhi, Xlo, W, K, m0, n0, smem);

    float* sC = (float*)smem;
    int tid = threadIdx.x;
    int col = tid & 127, half_ = tid >> 7;
    float bsum = b1[n0 + col] + b2[n0 + col];
#pragma unroll 4
    for (int rr = 0; rr < 64; rr++) {
        int r = half_ * 64 + rr;
        C[(size_t)(m0 + r) * G4 + n0 + col] = sC[r * LDC + col] + bsum;
    }
}

// ---------------- fused LSTM recurrent step ----------------
// TOK=1: gate preacts gathered from 37-row table via token ids (layer 0)
// TOK=0: gate preacts read from xg (layer 1)
// WRITEY=0: skip y stores (encoder layer 1 — outputs dead, only state carries)
template<int TOK, int WRITEY>
__global__ __launch_bounds__(256, 2) void lstm_step_k(
    const __half* __restrict__ hhi_c, const __half* __restrict__ hlo_c,
    __half* __restrict__ hhi_n, __half* __restrict__ hlo_n,
    float* __restrict__ c_st,
    const __half* __restrict__ W,
    const float* __restrict__ xg, const float* __restrict__ tab, const int* __restrict__ toks,
    __half* __restrict__ yhi, __half* __restrict__ ylo,
    int t)
{
    extern __shared__ char smem[];
    int m0 = blockIdx.y * 128, n0 = blockIdx.x * 32;
    gemm_core<1>(hhi_c, hlo_c, W, HID, m0, n0, smem);

    float* sC = (float*)smem;
    int tid = threadIdx.x;
    int cc = tid & 31, msub = tid >> 5;
    int n = n0 + cc;
    int cl = (cc & 15) + ((cc >> 4) << 6);
#pragma unroll 4
    for (int rr = 0; rr < 16; rr++) {
        int r = msub * 16 + rr;
        int gm = m0 + r;
        float di = sC[r * LDC + cl];
        float df = sC[r * LDC + cl + 16];
        float dg = sC[r * LDC + cl + 32];
        float dv = sC[r * LDC + cl + 48];
        float x0, x1, x2, x3;
        if (TOK) {
            int tk = toks[gm * SEQ + t];
            const float* tb = tab + (size_t)tk * G4 + n;
            x0 = tb[0]; x1 = tb[HID]; x2 = tb[2 * HID]; x3 = tb[3 * HID];
        } else {
            size_t xb = ((size_t)gm * SEQ + t) * G4 + n;
            x0 = xg[xb]; x1 = xg[xb + HID]; x2 = xg[xb + 2 * HID]; x3 = xg[xb + 3 * HID];
        }
        float iv = sig_ (di + x0);
        float fv = sig_ (df + x1);
        float gv = tanh_(dg + x2);
        float ov = sig_ (dv + x3);
        size_t ci = (size_t)gm * HID + n;
        float cn = fv * c_st[ci] + iv * gv;
        c_st[ci] = cn;
        float h = ov * tanh_(cn);
        __half hh, hl;
        split2h(h, hh, hl);
        hhi_n[ci] = hh; hlo_n[ci] = hl;
        if (WRITEY) {
            size_t yi = ((size_t)gm * SEQ + t) * HID + n;
            yhi[yi] = hh;   ylo[yi] = hl;
        }
    }
}

// ---------------- layer-0 gate table ----------------
__global__ void tab_k(const float* __restrict__ emb, const float* __restrict__ W,
                      const float* __restrict__ b1, const float* __restrict__ b2,
                      float* __restrict__ tab)
{
    __shared__ float es[EMB];
    int v = blockIdx.x;
    int g = blockIdx.y * 256 + threadIdx.x;
    for (int k = threadIdx.x; k < EMB; k += 256) es[k] = emb[v * EMB + k];
    __syncthreads();
    const float* wr = W + (size_t)g * EMB;
    float acc = 0.0f;
#pragma unroll 8
    for (int k = 0; k < EMB; k++) acc += es[k] * wr[k];
    tab[v * G4 + g] = acc + b1[g] + b2[g];
}

__global__ void dtok_k(const int* __restrict__ tgt, int* __restrict__ dtok) {
    int i = blockIdx.x * 256 + threadIdx.x;
    if (i < MROWS) {
        int t = i % SEQ;
        dtok[i] = (t == 0) ? 1 : tgt[i - 1];   // [SOS, tgt[:, :-1]]
    }
}

// ---------------- small kernels ----------------
__global__ void zero_u4(uint4* __restrict__ p, int n) {
    int i = blockIdx.x * 256 + threadIdx.x;
    if (i < n) p[i] = make_uint4(0, 0, 0, 0);
}

__global__ void convh_k(const float* __restrict__ s, __half* __restrict__ w, int n) {
    int i = (blockIdx.x * 256 + threadIdx.x) * 4;
    if (i < n) {
        float4 v = *(const float4*)(s + i);
        __half2* p = (__half2*)(w + i);
        p[0] = __floats2half2_rn(v.x, v.y);
        p[1] = __floats2half2_rn(v.z, v.w);
    }
}

// ---------------- final projection: out = (Yhi+Ylo) @ fcW^T + fcb ----------------
__global__ __launch_bounds__(128) void fc_k(
    const __half* __restrict__ Yhi, const __half* __restrict__ Ylo,
    const float* __restrict__ W, const float* __restrict__ bias, float* __restrict__ out)
{
    __shared__ float As[128][33];
    __shared__ float Ws[32][40];
    int tid = threadIdx.x;
    int row0 = blockIdx.x * 128;

    float acc[VOC];
#pragma unroll
    for (int v = 0; v < VOC; v++) acc[v] = 0.0f;

    for (int k0 = 0; k0 < HID; k0 += 32) {
#pragma unroll
        for (int i = 0; i < 8; i++) {
            int f = i * 128 + tid;
            int r = f >> 3, q = f & 7;
            const __half2* ph = (const __half2*)&Yhi[(size_t)(row0 + r) * HID + k0 + q * 4];
            const __half2* pl = (const __half2*)&Ylo[(size_t)(row0 + r) * HID + k0 + q * 4];
            float2 h0 = __half22float2(ph[0]), h1 = __half22float2(ph[1]);
            float2 l0 = __half22float2(pl[0]), l1 = __half22float2(pl[1]);
            As[r][q * 4 + 0] = h0.x + l0.x; As[r][q * 4 + 1] = h0.y + l0.y;
            As[r][q * 4 + 2] = h1.x + l1.x; As[r][q * 4 + 3] = h1.y + l1.y;
        }
        for (int l = tid; l < VOC * 32; l += 128) {
            int v = l >> 5, kk = l & 31;
            Ws[kk][v] = W[(size_t)v * HID + k0 + kk];
        }
        __syncthreads();
#pragma unroll
        for (int kk = 0; kk < 32; kk++) {
            float a = As[tid][kk];
#pragma unroll
            for (int v = 0; v < VOC; v++) acc[v] += a * Ws[kk][v];
        }
        __syncthreads();
    }
    int row = row0 + tid;
#pragma unroll
    for (int v = 0; v < VOC; v++)
        out[(size_t)row * VOC + v] = acc[v] + bias[v];
}

// ---------------- driver ----------------
extern "C" void kernel_launch(void* const* d_in, const int* in_sizes, int n_in,
                              void* d_out, int out_size)
{
    const int*   src    = (const int*)  d_in[0];
    const int*   tgt    = (const int*)  d_in[1];
    const float* emb    = (const float*)d_in[2];
    const float* eW_ih0 = (const float*)d_in[3];
    const float* eW_hh0 = (const float*)d_in[4];
    const float* eb_ih0 = (const float*)d_in[5];
    const float* eb_hh0 = (const float*)d_in[6];
    const float* eW_ih1 = (const float*)d_in[7];
    const float* eW_hh1 = (const float*)d_in[8];
    const float* eb_ih1 = (const float*)d_in[9];
    const float* eb_hh1 = (const float*)d_in[10];
    const float* dW_ih0 = (const float*)d_in[11];
    const float* dW_hh0 = (const float*)d_in[12];
    const float* db_ih0 = (const float*)d_in[13];
    const float* db_hh0 = (const float*)d_in[14];
    const float* dW_ih1 = (const float*)d_in[15];
    const float* dW_hh1 = (const float*)d_in[16];
    const float* db_ih1 = (const float*)d_in[17];
    const float* db_hh1 = (const float*)d_in[18];
    const float* fcW    = (const float*)d_in[19];
    const float* fcb    = (const float*)d_in[20];
    float* out = (float*)d_out;

    // Second stream + events for enc1 || dec0 overlap (created once; work is
    // identical on every call, so capture sees the same graph each time).
    static cudaStream_t s2 = nullptr;
    static cudaEvent_t evF = nullptr, evJ = nullptr;
    if (!s2) {
        cudaStreamCreate(&s2);
        cudaEventCreateWithFlags(&evF, cudaEventDisableTiming);
        cudaEventCreateWithFlags(&evJ, cudaEventDisableTiming);
    }

    cudaFuncSetAttribute(gemm_in_k,        cudaFuncAttributeMaxDynamicSharedMemorySize, SMEM_ALLOC);
    cudaFuncSetAttribute(lstm_step_k<0,0>, cudaFuncAttributeMaxDynamicSharedMemorySize, SMEM_ALLOC);
    cudaFuncSetAttribute(lstm_step_k<0,1>, cudaFuncAttributeMaxDynamicSharedMemorySize, SMEM_ALLOC);
    cudaFuncSetAttribute(lstm_step_k<1,1>, cudaFuncAttributeMaxDynamicSharedMemorySize, SMEM_ALLOC);

    float *xg, *c0, *c1, *tabE, *tabD;
    int* dtok;
    __half *yhi, *ylo, *w;
    __half *h0hi_a, *h0lo_a, *h0hi_b, *h0lo_b, *h1hi_a, *h1lo_a, *h1hi_b, *h1lo_b;
    cudaGetSymbolAddress((void**)&xg,   g_xg);
    cudaGetSymbolAddress((void**)&yhi,  g_yhi);
    cudaGetSymbolAddress((void**)&ylo,  g_ylo);
    cudaGetSymbolAddress((void**)&w,    g_w);
    cudaGetSymbolAddress((void**)&tabE, g_tabE);
    cudaGetSymbolAddress((void**)&tabD, g_tabD);
    cudaGetSymbolAddress((void**)&dtok, g_dtok);
    cudaGetSymbolAddress((void**)&h0hi_a, g_h0hi_a);
    cudaGetSymbolAddress((void**)&h0lo_a, g_h0lo_a);
    cudaGetSymbolAddress((void**)&h0hi_b, g_h0hi_b);
    cudaGetSymbolAddress((void**)&h0lo_b, g_h0lo_b);
    cudaGetSymbolAddress((void**)&h1hi_a, g_h1hi_a);
    cudaGetSymbolAddress((void**)&h1lo_a, g_h1lo_a);
    cudaGetSymbolAddress((void**)&h1hi_b, g_h1hi_b);
    cudaGetSymbolAddress((void**)&h1lo_b, g_h1lo_b);
    cudaGetSymbolAddress((void**)&c0, g_c0);
    cudaGetSymbolAddress((void**)&c1, g_c1);

    const size_t WSLOT = (size_t)G4 * HID;

    // ---- weight conversion to fp16 (6 slots) ----
    {
        int n2 = G4 * HID;
        int b2 = n2 / 1024;
        convh_k<<<b2, 256>>>(eW_hh0, w + 0 * WSLOT, n2);
        convh_k<<<b2, 256>>>(eW_ih1, w + 1 * WSLOT, n2);
        convh_k<<<b2, 256>>>(eW_hh1, w + 2 * WSLOT, n2);
        convh_k<<<b2, 256>>>(dW_hh0, w + 3 * WSLOT, n2);
        convh_k<<<b2, 256>>>(dW_ih1, w + 4 * WSLOT, n2);
        convh_k<<<b2, 256>>>(dW_hh1, w + 5 * WSLOT, n2);
    }
    // ---- layer-0 gate tables (exact fp32) + decoder tokens ----
    {
        dim3 tg(VOC, G4 / 256);
        tab_k<<<tg, 256>>>(emb, eW_ih0, eb_ih0, eb_hh0, tabE);
        tab_k<<<tg, 256>>>(emb, dW_ih0, db_ih0, db_hh0, tabD);
        dtok_k<<<(MROWS + 255) / 256, 256>>>(tgt, dtok);
    }
    // ---- zero initial states ----
    {
        int nb = BATCH * HID * 2 / 16;
        int nf = BATCH * HID * 4 / 16;
        zero_u4<<<(nb + 255) / 256, 256>>>((uint4*)h0hi_a, nb);
        zero_u4<<<(nb + 255) / 256, 256>>>((uint4*)h0lo_a, nb);
        zero_u4<<<(nb + 255) / 256, 256>>>((uint4*)h1hi_a, nb);
        zero_u4<<<(nb + 255) / 256, 256>>>((uint4*)h1lo_a, nb);
        zero_u4<<<(nf + 255) / 256, 256>>>((uint4*)c0, nf);
        zero_u4<<<(nf + 255) / 256, 256>>>((uint4*)c1, nf);
    }

    dim3 ggrid(G4 / 128, MROWS / 128);   // (32, 384)
    dim3 sgrid(HID / 32, BATCH / 128);   // (32, 16)

    __half *hc0h = h0hi_a, *hc0l = h0lo_a, *hn0h = h0hi_b, *hn0l = h0lo_b;
    __half *hc1h = h1hi_a, *hc1l = h1lo_a, *hn1h = h1hi_b, *hn1l = h1lo_b;

    // ---- encoder layer 0 (table path, writes y) ----
    for (int t = 0; t < SEQ; t++) {
        lstm_step_k<1,1><<<sgrid, 256, SMEM_ALLOC>>>(hc0h, hc0l, hn0h, hn0l, c0,
                                                     w + 0 * WSLOT,
                                                     (const float*)nullptr, tabE, src,
                                                     yhi, ylo, t);
        __half* t1 = hc0h; hc0h = hn0h; hn0h = t1;
        __half* t2 = hc0l; hc0l = hn0l; hn0l = t2;
    }
    // ---- encoder layer-1 projection (consumes enc0 y) ----
    gemm_in_k<<<ggrid, 256, SMEM_ALLOC>>>(yhi, ylo, w + 1 * WSLOT, eb_ih1, eb_hh1, xg, HID);

    // ---- fork: dec0 (stream s2) runs concurrently with enc1 (default stream) ----
    // dec0 needs enc0's final (h0,c0) and must not clobber y until proj1 read it.
    cudaEventRecord(evF, 0);
    cudaStreamWaitEvent(s2, evF, 0);

    // stream s2: decoder layer 0 (table path; writes y for dec1 projection)
    for (int t = 0; t < SEQ; t++) {
        lstm_step_k<1,1><<<sgrid, 256, SMEM_ALLOC, s2>>>(hc0h, hc0l, hn0h, hn0l, c0,
                                                         w + 3 * WSLOT,
                                                         (const float*)nullptr, tabD, dtok,
                                                         yhi, ylo, t);
        __half* t1 = hc0h; hc0h = hn0h; hn0h = t1;
        __half* t2 = hc0l; hc0l = hn0l; hn0l = t2;
    }
    cudaEventRecord(evJ, s2);

    // default stream: encoder layer 1 (y writes dead — only state carries)
    for (int t = 0; t < SEQ; t++) {
        lstm_step_k<0,0><<<sgrid, 256, SMEM_ALLOC>>>(hc1h, hc1l, hn1h, hn1l, c1,
                                                     w + 2 * WSLOT,
                                                     xg, (const float*)nullptr, (const int*)nullptr,
                                                     (__half*)nullptr, (__half*)nullptr, t);
        __half* t1 = hc1h; hc1h = hn1h; hn1h = t1;
        __half* t2 = hc1l; hc1l = hn1l; hn1l = t2;
    }

    // ---- join: dec1 projection needs dec0's y ----
    cudaStreamWaitEvent(0, evJ, 0);
    gemm_in_k<<<ggrid, 256, SMEM_ALLOC>>>(yhi, ylo, w + 4 * WSLOT, db_ih1, db_hh1, xg, HID);

    // ---- decoder layer 1 (writes y for FC) ----
    for (int t = 0; t < SEQ; t++) {
        lstm_step_k<0,1><<<sgrid, 256, SMEM_ALLOC>>>(hc1h, hc1l, hn1h, hn1l, c1,
                                                     w + 5 * WSLOT,
                                                     xg, (const float*)nullptr, (const int*)nullptr,
                                                     yhi, ylo, t);
        __half* t1 = hc1h; hc1h = hn1h; hn1h = t1;
        __half* t2 = hc1l; hc1l = hn1l; hn1l = t2;
    }
    // ---- output projection ----
    fc_k<<<MROWS / 128, 128>>>(yhi, ylo, fcW, fcb, out);
}